// round 1
// baseline (speedup 1.0000x reference)
#include <cuda_runtime.h>
#include <cuda_bf16.h>
#include <math.h>

#define Bc 4
#define Nn 2048
#define Mm 1024
#define Dd 512
#define Hh 8
#define DK 64
#define SCALE 0.125f
#define NEGV -9e15f

// ---------------- scratch (static device memory; no allocations) ------------
// Offsets in floats within one big scratch buffer.
#define OFF_QN    0ULL
#define OFF_KN    4194304ULL
#define OFF_VN    8388608ULL
#define OFF_QE    12582912ULL
#define OFF_KE    14680064ULL
#define OFF_VE    16777216ULL
#define OFF_EATTN 18874368ULL
#define OFF_ELN   20971520ULL
#define OFF_HID   23068672ULL
#define OFF_S     25165824ULL   /* 67108864 floats */
#define OFF_INCT  92274688ULL   /* 8388608 ints    */
#define SCRATCH_FLOATS 100663296ULL

__device__ float g_scratch[SCRATCH_FLOATS];

__device__ __forceinline__ float gelu_exact(float x) {
    return 0.5f * x * (1.0f + erff(x * 0.70710678118654752f));
}

// ---------------- incidence transpose: [B,N,M] -> [B,M,N] -------------------
__global__ __launch_bounds__(256) void transpose_inc(const int* __restrict__ inc,
                                                     int* __restrict__ incT) {
    __shared__ int t[32][33];
    int b  = blockIdx.z;
    int n0 = blockIdx.x * 32;
    int m0 = blockIdx.y * 32;
    for (int i = threadIdx.y; i < 32; i += 8)
        t[i][threadIdx.x] = inc[((size_t)b * Nn + n0 + i) * Mm + m0 + threadIdx.x];
    __syncthreads();
    for (int i = threadIdx.y; i < 32; i += 8)
        incT[((size_t)b * Mm + m0 + i) * Nn + n0 + threadIdx.x] = t[threadIdx.x][i];
}

// ---------------- SGEMM: C[R,512] = act(A[R,512] @ W[512,512] + bias) -------
// Tile 64x64, BK=16, 256 threads, 4x4 register tile, float4 shared reads.
__global__ __launch_bounds__(256) void sgemm_bias(const float* __restrict__ A,
                                                  const float* __restrict__ W,
                                                  const float* __restrict__ bias,
                                                  float* __restrict__ C,
                                                  int act) {
    __shared__ float As[16][68];  // [k][m]
    __shared__ float Ws[16][68];  // [k][n]
    int tid = threadIdx.x;
    int tx = tid & 15, ty = tid >> 4;
    int row0 = blockIdx.y * 64, col0 = blockIdx.x * 64;

    float acc[4][4] = {};
    for (int kt = 0; kt < 512; kt += 16) {
#pragma unroll
        for (int i = 0; i < 4; i++) {
            int idx = tid + i * 256;
            int r = idx >> 4, kk = idx & 15;
            As[kk][r] = A[(size_t)(row0 + r) * 512 + kt + kk];
        }
#pragma unroll
        for (int i = 0; i < 4; i++) {
            int idx = tid + i * 256;
            int kk = idx >> 6, c = idx & 63;
            Ws[kk][c] = W[(size_t)(kt + kk) * 512 + col0 + c];
        }
        __syncthreads();
#pragma unroll
        for (int kk = 0; kk < 16; kk++) {
            float4 a  = *(const float4*)&As[kk][ty * 4];
            float4 bv = *(const float4*)&Ws[kk][tx * 4];
            acc[0][0] += a.x * bv.x; acc[0][1] += a.x * bv.y; acc[0][2] += a.x * bv.z; acc[0][3] += a.x * bv.w;
            acc[1][0] += a.y * bv.x; acc[1][1] += a.y * bv.y; acc[1][2] += a.y * bv.z; acc[1][3] += a.y * bv.w;
            acc[2][0] += a.z * bv.x; acc[2][1] += a.z * bv.y; acc[2][2] += a.z * bv.z; acc[2][3] += a.z * bv.w;
            acc[3][0] += a.w * bv.x; acc[3][1] += a.w * bv.y; acc[3][2] += a.w * bv.z; acc[3][3] += a.w * bv.w;
        }
        __syncthreads();
    }
    int colb = col0 + tx * 4;
    float4 bvec = *(const float4*)&bias[colb];
#pragma unroll
    for (int i = 0; i < 4; i++) {
        int row = row0 + ty * 4 + i;
        float4 v;
        v.x = acc[i][0] + bvec.x;
        v.y = acc[i][1] + bvec.y;
        v.z = acc[i][2] + bvec.z;
        v.w = acc[i][3] + bvec.w;
        if (act) { v.x = gelu_exact(v.x); v.y = gelu_exact(v.y); v.z = gelu_exact(v.z); v.w = gelu_exact(v.w); }
        *(float4*)&C[(size_t)row * 512 + colb] = v;
    }
}

// ---------------- attention scores with mask folded in ----------------------
// S[b,h,m,n] = mask[b,m,n] ? SCALE * dot(Q[b,m,h*64:], K[b,n,h*64:]) : NEG
// Q: [B,L1,512], K: [B,L2,512], mask: [B,L1,L2], S: [B,H,L1,L2]
__global__ __launch_bounds__(256) void attn_scores(const float* __restrict__ Q,
                                                   const float* __restrict__ K,
                                                   const int* __restrict__ mask,
                                                   float* __restrict__ S,
                                                   int L1, int L2) {
    __shared__ float Qs[64][68];
    __shared__ float Ks[64][68];
    int bh = blockIdx.z;
    int b = bh / Hh, h = bh - b * Hh;
    int m0 = blockIdx.y * 64, n0 = blockIdx.x * 64;
    int tid = threadIdx.x;
    int tx = tid & 15, ty = tid >> 4;

#pragma unroll
    for (int i = 0; i < 16; i++) {
        int idx = tid + i * 256;
        int r = idx >> 6, d = idx & 63;
        Qs[r][d] = Q[((size_t)b * L1 + m0 + r) * 512 + h * 64 + d];
    }
#pragma unroll
    for (int i = 0; i < 16; i++) {
        int idx = tid + i * 256;
        int r = idx >> 6, d = idx & 63;
        Ks[r][d] = K[((size_t)b * L2 + n0 + r) * 512 + h * 64 + d];
    }
    __syncthreads();

    float acc[4][4] = {};
#pragma unroll
    for (int k = 0; k < 64; k += 4) {
        float4 a[4], bb[4];
#pragma unroll
        for (int i = 0; i < 4; i++) a[i]  = *(const float4*)&Qs[ty + 16 * i][k];
#pragma unroll
        for (int j = 0; j < 4; j++) bb[j] = *(const float4*)&Ks[tx + 16 * j][k];
#pragma unroll
        for (int i = 0; i < 4; i++)
#pragma unroll
            for (int j = 0; j < 4; j++)
                acc[i][j] += a[i].x * bb[j].x + a[i].y * bb[j].y + a[i].z * bb[j].z + a[i].w * bb[j].w;
    }

#pragma unroll
    for (int i = 0; i < 4; i++) {
        int m = m0 + ty + 16 * i;
#pragma unroll
        for (int j = 0; j < 4; j++) {
            int n = n0 + tx + 16 * j;
            int mk = mask[((size_t)b * L1 + m) * L2 + n];
            S[(((size_t)bh) * L1 + m) * L2 + n] = (mk > 0) ? acc[i][j] * SCALE : NEGV;
        }
    }
}

// ---------------- row softmax (in place) -------------------------------------
__global__ __launch_bounds__(256) void softmax_rows(float* __restrict__ S, int L2) {
    extern __shared__ float buf[];
    __shared__ float red[256];
    int tid = threadIdx.x;
    float* p = S + (size_t)blockIdx.x * L2;

    float mx = -3.4e38f;
    for (int i = tid; i < L2; i += 256) { float v = p[i]; buf[i] = v; mx = fmaxf(mx, v); }
    red[tid] = mx; __syncthreads();
    for (int s = 128; s > 0; s >>= 1) { if (tid < s) red[tid] = fmaxf(red[tid], red[tid + s]); __syncthreads(); }
    mx = red[0]; __syncthreads();

    float sum = 0.0f;
    for (int i = tid; i < L2; i += 256) { float e = expf(buf[i] - mx); buf[i] = e; sum += e; }
    red[tid] = sum; __syncthreads();
    for (int s = 128; s > 0; s >>= 1) { if (tid < s) red[tid] += red[tid + s]; __syncthreads(); }
    float inv = 1.0f / red[0];
    __syncthreads();
    for (int i = tid; i < L2; i += 256) p[i] = buf[i] * inv;
}

// ---------------- output = gelu(P @ V_headslice) -----------------------------
// P: [B,H,L1,L2], V: [B,L2,512], Out: [B,L1,512] (writes head slice h*64..)
__global__ __launch_bounds__(256) void attn_out(const float* __restrict__ P,
                                                const float* __restrict__ V,
                                                float* __restrict__ Out,
                                                int L1, int L2) {
    __shared__ float Ps[32][68];
    __shared__ float Vs[64][65];
    int bh = blockIdx.y;
    int b = bh / Hh, h = bh - b * Hh;
    int m0 = blockIdx.x * 32;
    int tid = threadIdx.x;
    int c = tid & 63, ty = tid >> 6;   // ty in 0..3

    float acc[8] = {};
    for (int n0 = 0; n0 < L2; n0 += 64) {
#pragma unroll
        for (int i = 0; i < 8; i++) {
            int idx = tid + i * 256;
            int r = idx >> 6, k = idx & 63;
            Ps[r][k] = P[(((size_t)bh) * L1 + m0 + r) * L2 + n0 + k];
        }
#pragma unroll
        for (int i = 0; i < 16; i++) {
            int idx = tid + i * 256;
            int k = idx >> 6, d = idx & 63;
            Vs[k][d] = V[((size_t)b * L2 + n0 + k) * 512 + h * 64 + d];
        }
        __syncthreads();
#pragma unroll
        for (int k = 0; k < 64; k += 4) {
            float v0 = Vs[k][c], v1 = Vs[k + 1][c], v2 = Vs[k + 2][c], v3 = Vs[k + 3][c];
#pragma unroll
            for (int i = 0; i < 8; i++) {
                float4 pv = *(const float4*)&Ps[ty + 4 * i][k];
                acc[i] += pv.x * v0 + pv.y * v1 + pv.z * v2 + pv.w * v3;
            }
        }
        __syncthreads();
    }
#pragma unroll
    for (int i = 0; i < 8; i++) {
        int m = m0 + ty + 4 * i;
        Out[((size_t)b * L1 + m) * 512 + h * 64 + c] = gelu_exact(acc[i]);
    }
}

// ---------------- layernorm(E + A) -------------------------------------------
__global__ __launch_bounds__(256) void ln_residual(const float* __restrict__ E,
                                                   const float* __restrict__ A,
                                                   const float* __restrict__ g,
                                                   const float* __restrict__ bb,
                                                   float* __restrict__ Out) {
    __shared__ float s1[256], s2[256];
    int tid = threadIdx.x;
    size_t base = (size_t)blockIdx.x * 512;
    float x0 = E[base + tid] + A[base + tid];
    float x1 = E[base + tid + 256] + A[base + tid + 256];
    s1[tid] = x0 + x1;
    s2[tid] = x0 * x0 + x1 * x1;
    __syncthreads();
    for (int s = 128; s > 0; s >>= 1) {
        if (tid < s) { s1[tid] += s1[tid + s]; s2[tid] += s2[tid + s]; }
        __syncthreads();
    }
    float mu  = s1[0] * (1.0f / 512.0f);
    float var = s2[0] * (1.0f / 512.0f) - mu * mu;
    float inv = rsqrtf(var + 1e-7f);
    Out[base + tid]       = (x0 - mu) * inv * g[tid]       + bb[tid];
    Out[base + tid + 256] = (x1 - mu) * inv * g[tid + 256] + bb[tid + 256];
}

// =============================================================================
extern "C" void kernel_launch(void* const* d_in, const int* in_sizes, int n_in,
                              void* d_out, int out_size) {
    const float* X    = (const float*)d_in[0];
    const int*   inc  = (const int*)d_in[1];
    const float* E    = (const float*)d_in[3];
    const float* Wqn  = (const float*)d_in[4];   const float* bqn = (const float*)d_in[5];
    const float* Wkn  = (const float*)d_in[6];   const float* bkn = (const float*)d_in[7];
    const float* Wvn  = (const float*)d_in[8];   const float* bvn = (const float*)d_in[9];
    const float* Wqe  = (const float*)d_in[10];  const float* bqe = (const float*)d_in[11];
    const float* Wke  = (const float*)d_in[12];  const float* bke = (const float*)d_in[13];
    const float* Wve  = (const float*)d_in[14];  const float* bve = (const float*)d_in[15];
    const float* Wm1  = (const float*)d_in[16];  const float* bm1 = (const float*)d_in[17];
    const float* Wm2  = (const float*)d_in[18];  const float* bm2 = (const float*)d_in[19];
    const float* g_ln = (const float*)d_in[20];  const float* b_ln = (const float*)d_in[21];

    float* out  = (float*)d_out;
    float* Xout = out;                              // [B,N,512]
    float* Eout = out + (size_t)Bc * Nn * Dd;       // [B,M,512]

    float* sc = nullptr;
    cudaGetSymbolAddress((void**)&sc, g_scratch);
    float* Qn    = sc + OFF_QN;
    float* Kn    = sc + OFF_KN;
    float* Vn    = sc + OFF_VN;
    float* Qe    = sc + OFF_QE;
    float* Ke    = sc + OFF_KE;
    float* Ve    = sc + OFF_VE;
    float* Eattn = sc + OFF_EATTN;
    float* Eln   = sc + OFF_ELN;
    float* Hid   = sc + OFF_HID;
    float* Smat  = sc + OFF_S;
    int*   incT  = (int*)(sc + OFF_INCT);

    // incidence transpose [B,N,M] -> [B,M,N]
    transpose_inc<<<dim3(Nn / 32, Mm / 32, Bc), dim3(32, 8)>>>(inc, incT);

    // node projections (rows = B*N), edge query projection (rows = B*M)
    sgemm_bias<<<dim3(8, (Bc * Nn) / 64), 256>>>(X, Wqn, bqn, Qn, 0);
    sgemm_bias<<<dim3(8, (Bc * Nn) / 64), 256>>>(X, Wkn, bkn, Kn, 0);
    sgemm_bias<<<dim3(8, (Bc * Nn) / 64), 256>>>(X, Wvn, bvn, Vn, 0);
    sgemm_bias<<<dim3(8, (Bc * Mm) / 64), 256>>>(E, Wqe, bqe, Qe, 0);

    // stage 1: edges attend over nodes
    attn_scores<<<dim3(Nn / 64, Mm / 64, Bc * Hh), 256>>>(Qe, Kn, incT, Smat, Mm, Nn);
    softmax_rows<<<Bc * Hh * Mm, 256, Nn * sizeof(float)>>>(Smat, Nn);
    attn_out<<<dim3(Mm / 32, Bc * Hh), 256>>>(Smat, Vn, Eattn, Mm, Nn);

    // residual layernorm + MLP -> E_ (written straight into d_out tail)
    ln_residual<<<Bc * Mm, 256>>>(E, Eattn, g_ln, b_ln, Eln);
    sgemm_bias<<<dim3(8, (Bc * Mm) / 64), 256>>>(Eln, Wm1, bm1, Hid, 1);
    sgemm_bias<<<dim3(8, (Bc * Mm) / 64), 256>>>(Hid, Wm2, bm2, Eout, 0);

    // edge K/V projections from final E_
    sgemm_bias<<<dim3(8, (Bc * Mm) / 64), 256>>>(Eout, Wke, bke, Ke, 0);
    sgemm_bias<<<dim3(8, (Bc * Mm) / 64), 256>>>(Eout, Wve, bve, Ve, 0);

    // stage 2: nodes attend over edges
    attn_scores<<<dim3(Mm / 64, Nn / 64, Bc * Hh), 256>>>(Qn, Ke, inc, Smat, Nn, Mm);
    softmax_rows<<<Bc * Hh * Nn, 256, Mm * sizeof(float)>>>(Smat, Mm);
    attn_out<<<dim3(Nn / 32, Bc * Hh), 256>>>(Smat, Ve, Xout, Nn, Mm);
}

// round 2
// speedup vs baseline: 1.1895x; 1.1895x over previous
#include <cuda_runtime.h>
#include <cuda_bf16.h>
#include <math.h>

#define Bc 4
#define Nn 2048
#define Mm 1024
#define Dd 512
#define Hh 8
#define DK 64
#define SCALE 0.125f
#define NEGV -9e15f

// ---------------- scratch (static device memory; no allocations) ------------
#define OFF_QN    0ULL
#define OFF_KN    4194304ULL
#define OFF_VN    8388608ULL
#define OFF_QE    12582912ULL
#define OFF_KE    14680064ULL
#define OFF_VE    16777216ULL
#define OFF_EATTN 18874368ULL
#define OFF_ELN   20971520ULL
#define OFF_HID   23068672ULL
#define SCRATCH_FLOATS 25165824ULL

__device__ float g_scratch[SCRATCH_FLOATS];

__device__ __forceinline__ float gelu_exact(float x) {
    return 0.5f * x * (1.0f + erff(x * 0.70710678118654752f));
}

// ---------------- SGEMM: C[R,512] = act(A[R,512] @ W[512,512] + bias) -------
__global__ __launch_bounds__(256) void sgemm_bias(const float* __restrict__ A,
                                                  const float* __restrict__ W,
                                                  const float* __restrict__ bias,
                                                  float* __restrict__ C,
                                                  int act) {
    __shared__ float As[16][68];  // [k][m]
    __shared__ float Ws[16][68];  // [k][n]
    int tid = threadIdx.x;
    int tx = tid & 15, ty = tid >> 4;
    int row0 = blockIdx.y * 64, col0 = blockIdx.x * 64;

    float acc[4][4] = {};
    for (int kt = 0; kt < 512; kt += 16) {
#pragma unroll
        for (int i = 0; i < 4; i++) {
            int idx = tid + i * 256;
            int r = idx >> 4, kk = idx & 15;
            As[kk][r] = A[(size_t)(row0 + r) * 512 + kt + kk];
        }
#pragma unroll
        for (int i = 0; i < 4; i++) {
            int idx = tid + i * 256;
            int kk = idx >> 6, c = idx & 63;
            Ws[kk][c] = W[(size_t)(kt + kk) * 512 + col0 + c];
        }
        __syncthreads();
#pragma unroll
        for (int kk = 0; kk < 16; kk++) {
            float4 a  = *(const float4*)&As[kk][ty * 4];
            float4 bv = *(const float4*)&Ws[kk][tx * 4];
            acc[0][0] += a.x * bv.x; acc[0][1] += a.x * bv.y; acc[0][2] += a.x * bv.z; acc[0][3] += a.x * bv.w;
            acc[1][0] += a.y * bv.x; acc[1][1] += a.y * bv.y; acc[1][2] += a.y * bv.z; acc[1][3] += a.y * bv.w;
            acc[2][0] += a.z * bv.x; acc[2][1] += a.z * bv.y; acc[2][2] += a.z * bv.z; acc[2][3] += a.z * bv.w;
            acc[3][0] += a.w * bv.x; acc[3][1] += a.w * bv.y; acc[3][2] += a.w * bv.z; acc[3][3] += a.w * bv.w;
        }
        __syncthreads();
    }
    int colb = col0 + tx * 4;
    float4 bvec = *(const float4*)&bias[colb];
#pragma unroll
    for (int i = 0; i < 4; i++) {
        int row = row0 + ty * 4 + i;
        float4 v;
        v.x = acc[i][0] + bvec.x;
        v.y = acc[i][1] + bvec.y;
        v.z = acc[i][2] + bvec.z;
        v.w = acc[i][3] + bvec.w;
        if (act) { v.x = gelu_exact(v.x); v.y = gelu_exact(v.y); v.z = gelu_exact(v.z); v.w = gelu_exact(v.w); }
        *(float4*)&C[(size_t)row * 512 + colb] = v;
    }
}

// ---------------- fused flash attention (scores + mask + softmax + PV + gelu)
// Q: [B,L1,512] head slice h, K/V: [B,L2,512] head slice h.
// mask element for (query i, key j) = inc[b][.][.]:
//   trans=0 : inc[(b*Nn + (q0+i))*Mm + (n0+j)]   (stage 2: query=node, key=edge)
//   trans=1 : inc[(b*Nn + (n0+j))*Mm + (q0+i)]   (stage 1: query=edge, key=node)
// Out[b, q, h*64 + d] = gelu( softmax-weighted V )
#define SMEM_TILE_B 17408                 // 64*68 floats
#define FLASH_SMEM (3 * SMEM_TILE_B + 64 * 65 * 4)

__global__ __launch_bounds__(256) void flash_attn(const float* __restrict__ Q,
                                                  const float* __restrict__ K,
                                                  const float* __restrict__ V,
                                                  const int* __restrict__ inc,
                                                  float* __restrict__ Out,
                                                  int L1, int L2, int trans) {
    extern __shared__ char smem[];
    float (*Qs)[68]  = (float(*)[68])(smem);
    float (*KVs)[68] = (float(*)[68])(smem + SMEM_TILE_B);
    float (*Ss)[68]  = (float(*)[68])(smem + 2 * SMEM_TILE_B);
    int   (*msk)[65] = (int(*)[65])  (smem + 3 * SMEM_TILE_B);

    int bh = blockIdx.y;
    int b = bh >> 3, h = bh & 7;
    int q0 = blockIdx.x * 64;
    int tid = threadIdx.x;
    int tx = tid & 15, ty = tid >> 4;
    const int* mbase = inc + (size_t)b * Nn * Mm;

    // load Q tile [64 x 64]
#pragma unroll
    for (int i = 0; i < 16; i++) {
        int idx = tid + i * 256;
        int r = idx >> 6, d = idx & 63;
        Qs[r][d] = Q[((size_t)b * L1 + q0 + r) * 512 + h * 64 + d];
    }

    float mrow[4], lrow[4], acc[4][4];
#pragma unroll
    for (int i = 0; i < 4; i++) {
        mrow[i] = -INFINITY; lrow[i] = 0.0f;
#pragma unroll
        for (int j = 0; j < 4; j++) acc[i][j] = 0.0f;
    }

    for (int n0 = 0; n0 < L2; n0 += 64) {
        // load K tile + mask tile
#pragma unroll
        for (int i = 0; i < 16; i++) {
            int idx = tid + i * 256;
            int r = idx >> 6, d = idx & 63;
            KVs[r][d] = K[((size_t)b * L2 + n0 + r) * 512 + h * 64 + d];
        }
        if (trans == 0) {
#pragma unroll
            for (int i = 0; i < 16; i++) {
                int idx = tid + i * 256;
                int r = idx >> 6, c = idx & 63;
                msk[r][c] = mbase[(size_t)(q0 + r) * Mm + n0 + c];
            }
        } else {
#pragma unroll
            for (int i = 0; i < 16; i++) {
                int idx = tid + i * 256;
                int c = idx >> 6, r = idx & 63;
                msk[r][c] = mbase[(size_t)(n0 + c) * Mm + q0 + r];
            }
        }
        __syncthreads();

        // S = Q @ K^T  (rows ty+16i, cols tx+16j)
        float s[4][4] = {};
#pragma unroll
        for (int k = 0; k < 64; k += 4) {
            float4 a[4], bb4[4];
#pragma unroll
            for (int i = 0; i < 4; i++) a[i]   = *(const float4*)&Qs[ty + 16 * i][k];
#pragma unroll
            for (int j = 0; j < 4; j++) bb4[j] = *(const float4*)&KVs[tx + 16 * j][k];
#pragma unroll
            for (int i = 0; i < 4; i++)
#pragma unroll
                for (int j = 0; j < 4; j++)
                    s[i][j] += a[i].x * bb4[j].x + a[i].y * bb4[j].y +
                               a[i].z * bb4[j].z + a[i].w * bb4[j].w;
        }

        // mask + scale
#pragma unroll
        for (int i = 0; i < 4; i++)
#pragma unroll
            for (int j = 0; j < 4; j++) {
                int mk = msk[ty + 16 * i][tx + 16 * j];
                s[i][j] = (mk > 0) ? s[i][j] * SCALE : NEGV;
            }

        // online softmax: rows live in 16-lane shuffle groups (same ty)
#pragma unroll
        for (int i = 0; i < 4; i++) {
            float tm = fmaxf(fmaxf(s[i][0], s[i][1]), fmaxf(s[i][2], s[i][3]));
            tm = fmaxf(tm, __shfl_xor_sync(0xffffffffu, tm, 8));
            tm = fmaxf(tm, __shfl_xor_sync(0xffffffffu, tm, 4));
            tm = fmaxf(tm, __shfl_xor_sync(0xffffffffu, tm, 2));
            tm = fmaxf(tm, __shfl_xor_sync(0xffffffffu, tm, 1));
            float mn = fmaxf(mrow[i], tm);
            float alpha = __expf(mrow[i] - mn);
            mrow[i] = mn;
            float rs = 0.0f;
#pragma unroll
            for (int j = 0; j < 4; j++) {
                float p = __expf(s[i][j] - mn);
                s[i][j] = p;
                rs += p;
            }
            rs += __shfl_xor_sync(0xffffffffu, rs, 8);
            rs += __shfl_xor_sync(0xffffffffu, rs, 4);
            rs += __shfl_xor_sync(0xffffffffu, rs, 2);
            rs += __shfl_xor_sync(0xffffffffu, rs, 1);
            lrow[i] = lrow[i] * alpha + rs;
#pragma unroll
            for (int j = 0; j < 4; j++) acc[i][j] *= alpha;
        }

        // write P tile
#pragma unroll
        for (int i = 0; i < 4; i++)
#pragma unroll
            for (int j = 0; j < 4; j++)
                Ss[ty + 16 * i][tx + 16 * j] = s[i][j];
        __syncthreads();  // K no longer needed, P fully written

        // load V tile transposed: KVs[d][n]
#pragma unroll
        for (int i = 0; i < 16; i++) {
            int idx = tid + i * 256;
            int n = idx >> 6, d = idx & 63;
            KVs[d][n] = V[((size_t)b * L2 + n0 + n) * 512 + h * 64 + d];
        }
        __syncthreads();

        // acc += P @ V  (out cols d = tx+16j; contraction over n)
#pragma unroll
        for (int k = 0; k < 64; k += 4) {
            float4 a[4], bb4[4];
#pragma unroll
            for (int i = 0; i < 4; i++) a[i]   = *(const float4*)&Ss[ty + 16 * i][k];
#pragma unroll
            for (int j = 0; j < 4; j++) bb4[j] = *(const float4*)&KVs[tx + 16 * j][k];
#pragma unroll
            for (int i = 0; i < 4; i++)
#pragma unroll
                for (int j = 0; j < 4; j++)
                    acc[i][j] += a[i].x * bb4[j].x + a[i].y * bb4[j].y +
                                 a[i].z * bb4[j].z + a[i].w * bb4[j].w;
        }
        __syncthreads();  // before next iteration overwrites tiles
    }

    // epilogue: normalize, gelu, write head slice
#pragma unroll
    for (int i = 0; i < 4; i++) {
        float inv = 1.0f / lrow[i];
        int r = q0 + ty + 16 * i;
#pragma unroll
        for (int j = 0; j < 4; j++) {
            int d = h * 64 + tx + 16 * j;
            Out[((size_t)b * L1 + r) * 512 + d] = gelu_exact(acc[i][j] * inv);
        }
    }
}

// ---------------- layernorm(E + A) -------------------------------------------
__global__ __launch_bounds__(256) void ln_residual(const float* __restrict__ E,
                                                   const float* __restrict__ A,
                                                   const float* __restrict__ g,
                                                   const float* __restrict__ bb,
                                                   float* __restrict__ Out) {
    __shared__ float s1[256], s2[256];
    int tid = threadIdx.x;
    size_t base = (size_t)blockIdx.x * 512;
    float x0 = E[base + tid] + A[base + tid];
    float x1 = E[base + tid + 256] + A[base + tid + 256];
    s1[tid] = x0 + x1;
    s2[tid] = x0 * x0 + x1 * x1;
    __syncthreads();
    for (int s = 128; s > 0; s >>= 1) {
        if (tid < s) { s1[tid] += s1[tid + s]; s2[tid] += s2[tid + s]; }
        __syncthreads();
    }
    float mu  = s1[0] * (1.0f / 512.0f);
    float var = s2[0] * (1.0f / 512.0f) - mu * mu;
    float inv = rsqrtf(var + 1e-7f);
    Out[base + tid]       = (x0 - mu) * inv * g[tid]       + bb[tid];
    Out[base + tid + 256] = (x1 - mu) * inv * g[tid + 256] + bb[tid + 256];
}

// =============================================================================
extern "C" void kernel_launch(void* const* d_in, const int* in_sizes, int n_in,
                              void* d_out, int out_size) {
    const float* X    = (const float*)d_in[0];
    const int*   inc  = (const int*)d_in[1];
    const float* E    = (const float*)d_in[3];
    const float* Wqn  = (const float*)d_in[4];   const float* bqn = (const float*)d_in[5];
    const float* Wkn  = (const float*)d_in[6];   const float* bkn = (const float*)d_in[7];
    const float* Wvn  = (const float*)d_in[8];   const float* bvn = (const float*)d_in[9];
    const float* Wqe  = (const float*)d_in[10];  const float* bqe = (const float*)d_in[11];
    const float* Wke  = (const float*)d_in[12];  const float* bke = (const float*)d_in[13];
    const float* Wve  = (const float*)d_in[14];  const float* bve = (const float*)d_in[15];
    const float* Wm1  = (const float*)d_in[16];  const float* bm1 = (const float*)d_in[17];
    const float* Wm2  = (const float*)d_in[18];  const float* bm2 = (const float*)d_in[19];
    const float* g_ln = (const float*)d_in[20];  const float* b_ln = (const float*)d_in[21];

    float* out  = (float*)d_out;
    float* Xout = out;                              // [B,N,512]
    float* Eout = out + (size_t)Bc * Nn * Dd;       // [B,M,512]

    float* sc = nullptr;
    cudaGetSymbolAddress((void**)&sc, g_scratch);
    float* Qn    = sc + OFF_QN;
    float* Kn    = sc + OFF_KN;
    float* Vn    = sc + OFF_VN;
    float* Qe    = sc + OFF_QE;
    float* Ke    = sc + OFF_KE;
    float* Ve    = sc + OFF_VE;
    float* Eattn = sc + OFF_EATTN;
    float* Eln   = sc + OFF_ELN;
    float* Hid   = sc + OFF_HID;

    static int smem_set = 0;
    if (!smem_set) {
        cudaFuncSetAttribute(flash_attn, cudaFuncAttributeMaxDynamicSharedMemorySize,
                             FLASH_SMEM);
        smem_set = 1;
    }

    // projections
    sgemm_bias<<<dim3(8, (Bc * Nn) / 64), 256>>>(X, Wqn, bqn, Qn, 0);
    sgemm_bias<<<dim3(8, (Bc * Nn) / 64), 256>>>(X, Wkn, bkn, Kn, 0);
    sgemm_bias<<<dim3(8, (Bc * Nn) / 64), 256>>>(X, Wvn, bvn, Vn, 0);
    sgemm_bias<<<dim3(8, (Bc * Mm) / 64), 256>>>(E, Wqe, bqe, Qe, 0);

    // stage 1: edges attend over nodes (fused)
    flash_attn<<<dim3(Mm / 64, Bc * Hh), 256, FLASH_SMEM>>>(Qe, Kn, Vn, inc, Eattn,
                                                            Mm, Nn, 1);

    // residual layernorm + MLP -> E_ (written straight into d_out tail)
    ln_residual<<<Bc * Mm, 256>>>(E, Eattn, g_ln, b_ln, Eln);
    sgemm_bias<<<dim3(8, (Bc * Mm) / 64), 256>>>(Eln, Wm1, bm1, Hid, 1);
    sgemm_bias<<<dim3(8, (Bc * Mm) / 64), 256>>>(Hid, Wm2, bm2, Eout, 0);

    // edge K/V projections from final E_
    sgemm_bias<<<dim3(8, (Bc * Mm) / 64), 256>>>(Eout, Wke, bke, Ke, 0);
    sgemm_bias<<<dim3(8, (Bc * Mm) / 64), 256>>>(Eout, Wve, bve, Ve, 0);

    // stage 2: nodes attend over edges (fused)
    flash_attn<<<dim3(Nn / 64, Bc * Hh), 256, FLASH_SMEM>>>(Qn, Ke, Ve, inc, Xout,
                                                            Nn, Mm, 0);
}

// round 3
// speedup vs baseline: 3.2568x; 2.7379x over previous
#include <cuda_runtime.h>
#include <cuda_bf16.h>
#include <math.h>
#include <stdint.h>

#define Bc 4
#define Nn 2048
#define Mm 1024
#define Dd 512
#define Hh 8
#define SCALE 0.125f
#define NEGV -9e15f

// ---------------- scratch (static device memory; no allocations) ------------
#define OFF_QN    0ULL
#define OFF_KN    4194304ULL
#define OFF_VN    8388608ULL
#define OFF_QE    12582912ULL
#define OFF_KE    14680064ULL
#define OFF_VE    16777216ULL
#define OFF_EATTN 18874368ULL
#define OFF_ELN   20971520ULL
#define OFF_HID   23068672ULL
#define OFF_PKO   25165824ULL   /* 262144 u32 : [B][N][M/32]  */
#define OFF_PKT   25427968ULL   /* 262144 u32 : [B][M][N/32]  */
#define SCRATCH_FLOATS 25690112ULL

__device__ float g_scratch[SCRATCH_FLOATS];

__device__ __forceinline__ float gelu_exact(float x) {
    return 0.5f * x * (1.0f + erff(x * 0.70710678118654752f));
}

__device__ __forceinline__ uint32_t f2tf(float x) {
    uint32_t u;
    asm("cvt.rna.tf32.f32 %0, %1;" : "=r"(u) : "f"(x));
    return u;
}

__device__ __forceinline__ void mma8(float d[4], const uint32_t a[4],
                                     uint32_t b0, uint32_t b1) {
    asm volatile("mma.sync.aligned.m16n8k8.row.col.f32.tf32.tf32.f32 "
                 "{%0,%1,%2,%3}, {%4,%5,%6,%7}, {%8,%9}, {%0,%1,%2,%3};"
                 : "+f"(d[0]), "+f"(d[1]), "+f"(d[2]), "+f"(d[3])
                 : "r"(a[0]), "r"(a[1]), "r"(a[2]), "r"(a[3]),
                   "r"(b0), "r"(b1));
}

// ---------------- bit-pack masks ---------------------------------------------
// pkO[b][n][mw] bit j = inc[b][n][mw*32+j] > 0   (keys = edges, natural)
__global__ __launch_bounds__(256) void pack_mask(const int* __restrict__ inc,
                                                 uint32_t* __restrict__ pk) {
    int w = blockIdx.x * 256 + threadIdx.x;      // word over [B*N][M/32]
    int row = w >> 5, mw = w & 31;
    const int4* p = (const int4*)(inc + (size_t)row * Mm + mw * 32);
    uint32_t v = 0;
#pragma unroll
    for (int i = 0; i < 8; i++) {
        int4 q = p[i];
        v |= (q.x > 0 ? 1u : 0u) << (i * 4 + 0);
        v |= (q.y > 0 ? 1u : 0u) << (i * 4 + 1);
        v |= (q.z > 0 ? 1u : 0u) << (i * 4 + 2);
        v |= (q.w > 0 ? 1u : 0u) << (i * 4 + 3);
    }
    pk[w] = v;
}

// pkT[b][m][nw] bit j = inc[b][nw*32+j][m] > 0   (keys = nodes, transposed)
__global__ void pack_maskT(const int* __restrict__ inc,
                           uint32_t* __restrict__ pk) {
    __shared__ int t[32][33];
    int b  = blockIdx.z;
    int n0 = blockIdx.x * 32;
    int m0 = blockIdx.y * 32;
    int tx = threadIdx.x, ty = threadIdx.y;
    for (int i = ty; i < 32; i += 8)
        t[i][tx] = inc[((size_t)b * Nn + n0 + i) * Mm + m0 + tx];
    __syncthreads();
    if (ty == 0) {
        uint32_t v = 0;
#pragma unroll
        for (int i = 0; i < 32; i++)
            v |= (t[i][tx] > 0 ? 1u : 0u) << i;
        pk[((size_t)b * Mm + m0 + tx) * (Nn / 32) + (n0 >> 5)] = v;
    }
}

// ---------------- tf32 tensor-core SGEMM: C[R,512] = act(A@W + bias) ---------
// block 128x64, 8 warps (warp = 16 rows x 64 cols), BK=32
__global__ __launch_bounds__(256) void sgemm_tc(const float* __restrict__ A,
                                                const float* __restrict__ W,
                                                const float* __restrict__ bias,
                                                float* __restrict__ C,
                                                int act) {
    __shared__ uint32_t As[128][36];
    __shared__ uint32_t Ws[32][68];
    int tid = threadIdx.x;
    int w = tid >> 5, lane = tid & 31;
    int r = lane >> 2, c = lane & 3;
    int row0 = blockIdx.y * 128, col0 = blockIdx.x * 64;

    float acc[8][4];
#pragma unroll
    for (int nt = 0; nt < 8; nt++)
#pragma unroll
        for (int j = 0; j < 4; j++) acc[nt][j] = 0.0f;

    for (int kt = 0; kt < 512; kt += 32) {
        __syncthreads();
#pragma unroll
        for (int i = 0; i < 4; i++) {
            int lin = tid + i * 256;
            int m = lin >> 3, k4 = (lin & 7) * 4;
            float4 v = *(const float4*)&A[(size_t)(row0 + m) * 512 + kt + k4];
            *(uint4*)&As[m][k4] = make_uint4(f2tf(v.x), f2tf(v.y), f2tf(v.z), f2tf(v.w));
        }
#pragma unroll
        for (int i = 0; i < 2; i++) {
            int lin = tid + i * 256;
            int k = lin >> 4, n4 = (lin & 15) * 4;
            float4 v = *(const float4*)&W[(size_t)(kt + k) * 512 + col0 + n4];
            *(uint4*)&Ws[k][n4] = make_uint4(f2tf(v.x), f2tf(v.y), f2tf(v.z), f2tf(v.w));
        }
        __syncthreads();
#pragma unroll
        for (int ks = 0; ks < 4; ks++) {
            uint32_t a[4];
            a[0] = As[w * 16 + r][ks * 8 + c];
            a[1] = As[w * 16 + r + 8][ks * 8 + c];
            a[2] = As[w * 16 + r][ks * 8 + c + 4];
            a[3] = As[w * 16 + r + 8][ks * 8 + c + 4];
#pragma unroll
            for (int nt = 0; nt < 8; nt++) {
                uint32_t b0 = Ws[ks * 8 + c][nt * 8 + r];
                uint32_t b1 = Ws[ks * 8 + c + 4][nt * 8 + r];
                mma8(acc[nt], a, b0, b1);
            }
        }
    }
#pragma unroll
    for (int nt = 0; nt < 8; nt++) {
        int col = col0 + nt * 8 + 2 * c;
        float2 bv = *(const float2*)&bias[col];
        int row = row0 + w * 16 + r;
        float2 v0, v1;
        v0.x = acc[nt][0] + bv.x; v0.y = acc[nt][1] + bv.y;
        v1.x = acc[nt][2] + bv.x; v1.y = acc[nt][3] + bv.y;
        if (act) {
            v0.x = gelu_exact(v0.x); v0.y = gelu_exact(v0.y);
            v1.x = gelu_exact(v1.x); v1.y = gelu_exact(v1.y);
        }
        *(float2*)&C[(size_t)row * 512 + col] = v0;
        *(float2*)&C[(size_t)(row + 8) * 512 + col] = v1;
    }
}

// ---------------- tf32 tensor-core flash attention ---------------------------
// 128 threads (4 warps), Q tile 64 rows, warp owns 16 rows x 64 cols.
// pk: bit-packed mask rows aligned with queries, bits along keys.
#define FLASH_SMEM ((64 * 68 + 64 * 72 + 64 * 68) * 4)

__global__ __launch_bounds__(128) void flash_tc(const float* __restrict__ Q,
                                                const float* __restrict__ K,
                                                const float* __restrict__ V,
                                                const uint32_t* __restrict__ pk,
                                                float* __restrict__ Out,
                                                int L1, int L2) {
    extern __shared__ uint32_t fsm[];
    uint32_t* KQ = fsm;                        // [64][68]
    uint32_t* Vs = fsm + 64 * 68;              // [64][72]
    uint32_t* Ps = fsm + 64 * 68 + 64 * 72;    // [64][68]

    int tid = threadIdx.x;
    int w = tid >> 5, lane = tid & 31;
    int r = lane >> 2, c = lane & 3;
    int w16 = w * 16;
    int bh = blockIdx.y;
    int b = bh >> 3, h = bh & 7;
    int q0 = blockIdx.x * 64;

    const float* Qb = Q + ((size_t)b * L1 + q0) * 512 + h * 64;
    const float* Kb = K + ((size_t)b * L2) * 512 + h * 64;
    const float* Vb = V + ((size_t)b * L2) * 512 + h * 64;
    int nw = L2 >> 5;
    const uint32_t* pr0 = pk + ((size_t)b * L1 + q0 + w16 + r) * nw;
    const uint32_t* pr1 = pk + ((size_t)b * L1 + q0 + w16 + r + 8) * nw;

    // stage Q into KQ, then load Q fragments to registers
#pragma unroll
    for (int i = 0; i < 8; i++) {
        int lin = tid + i * 128;
        int row = lin >> 4, c4 = (lin & 15) * 4;
        float4 v = *(const float4*)(Qb + (size_t)row * 512 + c4);
        *(uint4*)(KQ + row * 68 + c4) = make_uint4(f2tf(v.x), f2tf(v.y), f2tf(v.z), f2tf(v.w));
    }
    __syncthreads();

    uint32_t qa[8][4];
#pragma unroll
    for (int ks = 0; ks < 8; ks++) {
        qa[ks][0] = KQ[(w16 + r) * 68 + ks * 8 + c];
        qa[ks][1] = KQ[(w16 + r + 8) * 68 + ks * 8 + c];
        qa[ks][2] = KQ[(w16 + r) * 68 + ks * 8 + c + 4];
        qa[ks][3] = KQ[(w16 + r + 8) * 68 + ks * 8 + c + 4];
    }

    float o[8][4];
#pragma unroll
    for (int nt = 0; nt < 8; nt++)
#pragma unroll
        for (int j = 0; j < 4; j++) o[nt][j] = 0.0f;
    float m0r = -INFINITY, m1r = -INFINITY, l0 = 0.0f, l1 = 0.0f;

    for (int n0 = 0; n0 < L2; n0 += 64) {
        __syncthreads();
#pragma unroll
        for (int i = 0; i < 8; i++) {
            int lin = tid + i * 128;
            int row = lin >> 4, c4 = (lin & 15) * 4;
            float4 kv = *(const float4*)(Kb + (size_t)(n0 + row) * 512 + c4);
            *(uint4*)(KQ + row * 68 + c4) =
                make_uint4(f2tf(kv.x), f2tf(kv.y), f2tf(kv.z), f2tf(kv.w));
            float4 vv = *(const float4*)(Vb + (size_t)(n0 + row) * 512 + c4);
            *(uint4*)(Vs + row * 72 + c4) =
                make_uint4(f2tf(vv.x), f2tf(vv.y), f2tf(vv.z), f2tf(vv.w));
        }
        uint32_t w00 = __ldg(pr0 + (n0 >> 5)), w01 = __ldg(pr0 + (n0 >> 5) + 1);
        uint32_t w10 = __ldg(pr1 + (n0 >> 5)), w11 = __ldg(pr1 + (n0 >> 5) + 1);
        __syncthreads();

        // S = Q @ K^T
        float s[8][4];
#pragma unroll
        for (int nt = 0; nt < 8; nt++)
#pragma unroll
            for (int j = 0; j < 4; j++) s[nt][j] = 0.0f;
#pragma unroll
        for (int ks = 0; ks < 8; ks++) {
#pragma unroll
            for (int nt = 0; nt < 8; nt++) {
                uint32_t b0 = KQ[(nt * 8 + r) * 68 + ks * 8 + c];
                uint32_t b1 = KQ[(nt * 8 + r) * 68 + ks * 8 + c + 4];
                mma8(s[nt], qa[ks], b0, b1);
            }
        }

        // mask + scale
#pragma unroll
        for (int nt = 0; nt < 8; nt++) {
            int k0 = nt * 8 + 2 * c;
            uint32_t wr0 = (k0 < 32) ? w00 : w01;
            uint32_t wr1 = (k0 < 32) ? w10 : w11;
            int sh = k0 & 31;
            s[nt][0] = ((wr0 >> sh) & 1u)       ? s[nt][0] * SCALE : NEGV;
            s[nt][1] = ((wr0 >> (sh + 1)) & 1u) ? s[nt][1] * SCALE : NEGV;
            s[nt][2] = ((wr1 >> sh) & 1u)       ? s[nt][2] * SCALE : NEGV;
            s[nt][3] = ((wr1 >> (sh + 1)) & 1u) ? s[nt][3] * SCALE : NEGV;
        }

        // online softmax (rows r and r+8; 4 lanes per row -> xor 1, xor 2)
        float tm0 = -INFINITY, tm1 = -INFINITY;
#pragma unroll
        for (int nt = 0; nt < 8; nt++) {
            tm0 = fmaxf(tm0, fmaxf(s[nt][0], s[nt][1]));
            tm1 = fmaxf(tm1, fmaxf(s[nt][2], s[nt][3]));
        }
        tm0 = fmaxf(tm0, __shfl_xor_sync(0xffffffffu, tm0, 1));
        tm0 = fmaxf(tm0, __shfl_xor_sync(0xffffffffu, tm0, 2));
        tm1 = fmaxf(tm1, __shfl_xor_sync(0xffffffffu, tm1, 1));
        tm1 = fmaxf(tm1, __shfl_xor_sync(0xffffffffu, tm1, 2));
        float mn0 = fmaxf(m0r, tm0), mn1 = fmaxf(m1r, tm1);
        float a0 = __expf(m0r - mn0), a1 = __expf(m1r - mn1);
        m0r = mn0; m1r = mn1;

        float rs0 = 0.0f, rs1 = 0.0f;
#pragma unroll
        for (int nt = 0; nt < 8; nt++) {
            float p0 = __expf(s[nt][0] - mn0);
            float p1 = __expf(s[nt][1] - mn0);
            float p2 = __expf(s[nt][2] - mn1);
            float p3 = __expf(s[nt][3] - mn1);
            rs0 += p0 + p1; rs1 += p2 + p3;
            int col = nt * 8 + 2 * c;
            Ps[(w16 + r) * 68 + col]         = f2tf(p0);
            Ps[(w16 + r) * 68 + col + 1]     = f2tf(p1);
            Ps[(w16 + r + 8) * 68 + col]     = f2tf(p2);
            Ps[(w16 + r + 8) * 68 + col + 1] = f2tf(p3);
        }
        rs0 += __shfl_xor_sync(0xffffffffu, rs0, 1);
        rs0 += __shfl_xor_sync(0xffffffffu, rs0, 2);
        rs1 += __shfl_xor_sync(0xffffffffu, rs1, 1);
        rs1 += __shfl_xor_sync(0xffffffffu, rs1, 2);
        l0 = l0 * a0 + rs0;
        l1 = l1 * a1 + rs1;
#pragma unroll
        for (int nt = 0; nt < 8; nt++) {
            o[nt][0] *= a0; o[nt][1] *= a0;
            o[nt][2] *= a1; o[nt][3] *= a1;
        }
        __syncwarp();

        // O += P @ V
        uint32_t pa[8][4];
#pragma unroll
        for (int ks = 0; ks < 8; ks++) {
            pa[ks][0] = Ps[(w16 + r) * 68 + ks * 8 + c];
            pa[ks][1] = Ps[(w16 + r + 8) * 68 + ks * 8 + c];
            pa[ks][2] = Ps[(w16 + r) * 68 + ks * 8 + c + 4];
            pa[ks][3] = Ps[(w16 + r + 8) * 68 + ks * 8 + c + 4];
        }
#pragma unroll
        for (int ks = 0; ks < 8; ks++) {
#pragma unroll
            for (int nt = 0; nt < 8; nt++) {
                uint32_t b0 = Vs[(ks * 8 + c) * 72 + nt * 8 + r];
                uint32_t b1 = Vs[(ks * 8 + c + 4) * 72 + nt * 8 + r];
                mma8(o[nt], pa[ks], b0, b1);
            }
        }
    }

    // epilogue
    float inv0 = 1.0f / l0, inv1 = 1.0f / l1;
    float* Ob = Out + ((size_t)b * L1 + q0) * 512 + h * 64;
#pragma unroll
    for (int nt = 0; nt < 8; nt++) {
        int col = nt * 8 + 2 * c;
        float2 v0, v1;
        v0.x = gelu_exact(o[nt][0] * inv0);
        v0.y = gelu_exact(o[nt][1] * inv0);
        v1.x = gelu_exact(o[nt][2] * inv1);
        v1.y = gelu_exact(o[nt][3] * inv1);
        *(float2*)(Ob + (size_t)(w16 + r) * 512 + col) = v0;
        *(float2*)(Ob + (size_t)(w16 + r + 8) * 512 + col) = v1;
    }
}

// ---------------- layernorm(E + A) -------------------------------------------
__global__ __launch_bounds__(256) void ln_residual(const float* __restrict__ E,
                                                   const float* __restrict__ A,
                                                   const float* __restrict__ g,
                                                   const float* __restrict__ bb,
                                                   float* __restrict__ Out) {
    __shared__ float s1[256], s2[256];
    int tid = threadIdx.x;
    size_t base = (size_t)blockIdx.x * 512;
    float x0 = E[base + tid] + A[base + tid];
    float x1 = E[base + tid + 256] + A[base + tid + 256];
    s1[tid] = x0 + x1;
    s2[tid] = x0 * x0 + x1 * x1;
    __syncthreads();
    for (int s = 128; s > 0; s >>= 1) {
        if (tid < s) { s1[tid] += s1[tid + s]; s2[tid] += s2[tid + s]; }
        __syncthreads();
    }
    float mu  = s1[0] * (1.0f / 512.0f);
    float var = s2[0] * (1.0f / 512.0f) - mu * mu;
    float inv = rsqrtf(var + 1e-7f);
    Out[base + tid]       = (x0 - mu) * inv * g[tid]       + bb[tid];
    Out[base + tid + 256] = (x1 - mu) * inv * g[tid + 256] + bb[tid + 256];
}

// =============================================================================
extern "C" void kernel_launch(void* const* d_in, const int* in_sizes, int n_in,
                              void* d_out, int out_size) {
    const float* X    = (const float*)d_in[0];
    const int*   inc  = (const int*)d_in[1];
    const float* E    = (const float*)d_in[3];
    const float* Wqn  = (const float*)d_in[4];   const float* bqn = (const float*)d_in[5];
    const float* Wkn  = (const float*)d_in[6];   const float* bkn = (const float*)d_in[7];
    const float* Wvn  = (const float*)d_in[8];   const float* bvn = (const float*)d_in[9];
    const float* Wqe  = (const float*)d_in[10];  const float* bqe = (const float*)d_in[11];
    const float* Wke  = (const float*)d_in[12];  const float* bke = (const float*)d_in[13];
    const float* Wve  = (const float*)d_in[14];  const float* bve = (const float*)d_in[15];
    const float* Wm1  = (const float*)d_in[16];  const float* bm1 = (const float*)d_in[17];
    const float* Wm2  = (const float*)d_in[18];  const float* bm2 = (const float*)d_in[19];
    const float* g_ln = (const float*)d_in[20];  const float* b_ln = (const float*)d_in[21];

    float* out  = (float*)d_out;
    float* Xout = out;                              // [B,N,512]
    float* Eout = out + (size_t)Bc * Nn * Dd;       // [B,M,512]

    float* sc = nullptr;
    cudaGetSymbolAddress((void**)&sc, g_scratch);
    float* Qn    = sc + OFF_QN;
    float* Kn    = sc + OFF_KN;
    float* Vn    = sc + OFF_VN;
    float* Qe    = sc + OFF_QE;
    float* Ke    = sc + OFF_KE;
    float* Ve    = sc + OFF_VE;
    float* Eattn = sc + OFF_EATTN;
    float* Eln   = sc + OFF_ELN;
    float* Hid   = sc + OFF_HID;
    uint32_t* pkO = (uint32_t*)(sc + OFF_PKO);
    uint32_t* pkT = (uint32_t*)(sc + OFF_PKT);

    static int smem_set = 0;
    if (!smem_set) {
        cudaFuncSetAttribute(flash_tc, cudaFuncAttributeMaxDynamicSharedMemorySize,
                             FLASH_SMEM);
        smem_set = 1;
    }

    // bit-pack masks (both orientations)
    pack_mask<<<(Bc * Nn * (Mm / 32)) / 256, 256>>>(inc, pkO);
    pack_maskT<<<dim3(Nn / 32, Mm / 32, Bc), dim3(32, 8)>>>(inc, pkT);

    // projections
    sgemm_tc<<<dim3(8, (Bc * Nn) / 128), 256>>>(X, Wqn, bqn, Qn, 0);
    sgemm_tc<<<dim3(8, (Bc * Nn) / 128), 256>>>(X, Wkn, bkn, Kn, 0);
    sgemm_tc<<<dim3(8, (Bc * Nn) / 128), 256>>>(X, Wvn, bvn, Vn, 0);
    sgemm_tc<<<dim3(8, (Bc * Mm) / 128), 256>>>(E, Wqe, bqe, Qe, 0);

    // stage 1: edges attend over nodes
    flash_tc<<<dim3(Mm / 64, Bc * Hh), 128, FLASH_SMEM>>>(Qe, Kn, Vn, pkT, Eattn,
                                                          Mm, Nn);

    // residual layernorm + MLP -> E_ (into d_out tail)
    ln_residual<<<Bc * Mm, 256>>>(E, Eattn, g_ln, b_ln, Eln);
    sgemm_tc<<<dim3(8, (Bc * Mm) / 128), 256>>>(Eln, Wm1, bm1, Hid, 1);
    sgemm_tc<<<dim3(8, (Bc * Mm) / 128), 256>>>(Hid, Wm2, bm2, Eout, 0);

    // edge K/V projections from final E_
    sgemm_tc<<<dim3(8, (Bc * Mm) / 128), 256>>>(Eout, Wke, bke, Ke, 0);
    sgemm_tc<<<dim3(8, (Bc * Mm) / 128), 256>>>(Eout, Wve, bve, Ve, 0);

    // stage 2: nodes attend over edges
    flash_tc<<<dim3(Nn / 64, Bc * Hh), 128, FLASH_SMEM>>>(Qn, Ke, Ve, pkO, Xout,
                                                          Nn, Mm);
}

// round 4
// speedup vs baseline: 3.7596x; 1.1544x over previous
#include <cuda_runtime.h>
#include <cuda_bf16.h>
#include <math.h>
#include <stdint.h>

#define Bc 4
#define Nn 2048
#define Mm 1024
#define Dd 512
#define Hh 8
#define SCALE 0.125f
#define NEGV -9e15f

// ---------------- scratch (static device memory; no allocations) ------------
#define OFF_QN    0ULL
#define OFF_KN    4194304ULL
#define OFF_VN    8388608ULL
#define OFF_QE    12582912ULL
#define OFF_KE    14680064ULL
#define OFF_VE    16777216ULL
#define OFF_EATTN 18874368ULL
#define OFF_ELN   20971520ULL
#define OFF_HID   23068672ULL
#define OFF_PKO   25165824ULL   /* 262144 u32 : [B][N][M/32]  */
#define OFF_PKT   25427968ULL   /* 262144 u32 : [B][M][N/32]  */
#define SCRATCH_FLOATS 25690112ULL

__device__ float g_scratch[SCRATCH_FLOATS];

__device__ __forceinline__ float gelu_exact(float x) {
    return 0.5f * x * (1.0f + erff(x * 0.70710678118654752f));
}

__device__ __forceinline__ uint32_t f2tf(float x) {
    uint32_t u;
    asm("cvt.rna.tf32.f32 %0, %1;" : "=r"(u) : "f"(x));
    return u;
}

__device__ __forceinline__ void mma8(float d[4], const uint32_t a[4],
                                     uint32_t b0, uint32_t b1) {
    asm volatile("mma.sync.aligned.m16n8k8.row.col.f32.tf32.tf32.f32 "
                 "{%0,%1,%2,%3}, {%4,%5,%6,%7}, {%8,%9}, {%0,%1,%2,%3};"
                 : "+f"(d[0]), "+f"(d[1]), "+f"(d[2]), "+f"(d[3])
                 : "r"(a[0]), "r"(a[1]), "r"(a[2]), "r"(a[3]),
                   "r"(b0), "r"(b1));
}

// ---------------- bit-pack masks ---------------------------------------------
__global__ __launch_bounds__(256) void pack_mask(const int* __restrict__ inc,
                                                 uint32_t* __restrict__ pk) {
    int w = blockIdx.x * 256 + threadIdx.x;
    int row = w >> 5, mw = w & 31;
    const int4* p = (const int4*)(inc + (size_t)row * Mm + mw * 32);
    uint32_t v = 0;
#pragma unroll
    for (int i = 0; i < 8; i++) {
        int4 q = p[i];
        v |= (q.x > 0 ? 1u : 0u) << (i * 4 + 0);
        v |= (q.y > 0 ? 1u : 0u) << (i * 4 + 1);
        v |= (q.z > 0 ? 1u : 0u) << (i * 4 + 2);
        v |= (q.w > 0 ? 1u : 0u) << (i * 4 + 3);
    }
    pk[w] = v;
}

__global__ void pack_maskT(const int* __restrict__ inc,
                           uint32_t* __restrict__ pk) {
    __shared__ int t[32][33];
    int b  = blockIdx.z;
    int n0 = blockIdx.x * 32;
    int m0 = blockIdx.y * 32;
    int tx = threadIdx.x, ty = threadIdx.y;
    for (int i = ty; i < 32; i += 8)
        t[i][tx] = inc[((size_t)b * Nn + n0 + i) * Mm + m0 + tx];
    __syncthreads();
    if (ty == 0) {
        uint32_t v = 0;
#pragma unroll
        for (int i = 0; i < 32; i++)
            v |= (t[i][tx] > 0 ? 1u : 0u) << i;
        pk[((size_t)b * Mm + m0 + tx) * (Nn / 32) + (n0 >> 5)] = v;
    }
}

// ---------------- tf32 tensor-core SGEMM v2 ----------------------------------
// block 128x128, 8 warps in 4x2, warp tile 32x64 (2 m-subtiles x 8 n-subtiles)
__global__ __launch_bounds__(256) void sgemm_tc(const float* __restrict__ A,
                                                const float* __restrict__ W,
                                                const float* __restrict__ bias,
                                                float* __restrict__ C,
                                                int act) {
    __shared__ uint32_t As[128][36];   // [m][k], pad->stride%32==4
    __shared__ uint32_t Ws[32][136];   // [k][n], pad->stride%32==8 (conflict-free frags)
    int tid = threadIdx.x;
    int w = tid >> 5, lane = tid & 31;
    int r = lane >> 2, c = lane & 3;
    int wm = (w & 3) * 32;             // warp row offset in block
    int wn = (w >> 2) * 64;            // warp col offset in block
    int row0 = blockIdx.y * 128, col0 = blockIdx.x * 128;

    float acc[2][8][4];
#pragma unroll
    for (int mi = 0; mi < 2; mi++)
#pragma unroll
        for (int nt = 0; nt < 8; nt++)
#pragma unroll
            for (int j = 0; j < 4; j++) acc[mi][nt][j] = 0.0f;

    for (int kt = 0; kt < 512; kt += 32) {
        __syncthreads();
#pragma unroll
        for (int i = 0; i < 4; i++) {
            int lin = tid + i * 256;
            int m = lin >> 3, k4 = (lin & 7) * 4;
            float4 v = *(const float4*)&A[(size_t)(row0 + m) * 512 + kt + k4];
            *(uint4*)&As[m][k4] = make_uint4(f2tf(v.x), f2tf(v.y), f2tf(v.z), f2tf(v.w));
        }
#pragma unroll
        for (int i = 0; i < 4; i++) {
            int lin = tid + i * 256;
            int k = lin >> 5, n4 = (lin & 31) * 4;
            float4 v = *(const float4*)&W[(size_t)(kt + k) * 512 + col0 + n4];
            *(uint4*)&Ws[k][n4] = make_uint4(f2tf(v.x), f2tf(v.y), f2tf(v.z), f2tf(v.w));
        }
        __syncthreads();
#pragma unroll
        for (int ks = 0; ks < 4; ks++) {
            uint32_t a[2][4];
#pragma unroll
            for (int mi = 0; mi < 2; mi++) {
                int mr = wm + mi * 16;
                a[mi][0] = As[mr + r][ks * 8 + c];
                a[mi][1] = As[mr + r + 8][ks * 8 + c];
                a[mi][2] = As[mr + r][ks * 8 + c + 4];
                a[mi][3] = As[mr + r + 8][ks * 8 + c + 4];
            }
#pragma unroll
            for (int nt = 0; nt < 8; nt++) {
                uint32_t b0 = Ws[ks * 8 + c][wn + nt * 8 + r];
                uint32_t b1 = Ws[ks * 8 + c + 4][wn + nt * 8 + r];
                mma8(acc[0][nt], a[0], b0, b1);
                mma8(acc[1][nt], a[1], b0, b1);
            }
        }
    }
#pragma unroll
    for (int mi = 0; mi < 2; mi++) {
        int row = row0 + wm + mi * 16 + r;
#pragma unroll
        for (int nt = 0; nt < 8; nt++) {
            int col = col0 + wn + nt * 8 + 2 * c;
            float2 bv = *(const float2*)&bias[col];
            float2 v0, v1;
            v0.x = acc[mi][nt][0] + bv.x; v0.y = acc[mi][nt][1] + bv.y;
            v1.x = acc[mi][nt][2] + bv.x; v1.y = acc[mi][nt][3] + bv.y;
            if (act) {
                v0.x = gelu_exact(v0.x); v0.y = gelu_exact(v0.y);
                v1.x = gelu_exact(v1.x); v1.y = gelu_exact(v1.y);
            }
            *(float2*)&C[(size_t)row * 512 + col] = v0;
            *(float2*)&C[(size_t)(row + 8) * 512 + col] = v1;
        }
    }
}

// ---------------- tf32 tensor-core flash attention ---------------------------
#define FLASH_SMEM ((64 * 68 + 64 * 72 + 64 * 68) * 4)

__global__ __launch_bounds__(128) void flash_tc(const float* __restrict__ Q,
                                                const float* __restrict__ K,
                                                const float* __restrict__ V,
                                                const uint32_t* __restrict__ pk,
                                                float* __restrict__ Out,
                                                int L1, int L2) {
    extern __shared__ uint32_t fsm[];
    uint32_t* KQ = fsm;                        // [64][68]
    uint32_t* Vs = fsm + 64 * 68;              // [64][72]
    uint32_t* Ps = fsm + 64 * 68 + 64 * 72;    // [64][68]

    int tid = threadIdx.x;
    int w = tid >> 5, lane = tid & 31;
    int r = lane >> 2, c = lane & 3;
    int w16 = w * 16;
    int bh = blockIdx.y;
    int b = bh >> 3, h = bh & 7;
    int q0 = blockIdx.x * 64;

    const float* Qb = Q + ((size_t)b * L1 + q0) * 512 + h * 64;
    const float* Kb = K + ((size_t)b * L2) * 512 + h * 64;
    const float* Vb = V + ((size_t)b * L2) * 512 + h * 64;
    int nw = L2 >> 5;
    const uint32_t* pr0 = pk + ((size_t)b * L1 + q0 + w16 + r) * nw;
    const uint32_t* pr1 = pk + ((size_t)b * L1 + q0 + w16 + r + 8) * nw;

#pragma unroll
    for (int i = 0; i < 8; i++) {
        int lin = tid + i * 128;
        int row = lin >> 4, c4 = (lin & 15) * 4;
        float4 v = *(const float4*)(Qb + (size_t)row * 512 + c4);
        *(uint4*)(KQ + row * 68 + c4) = make_uint4(f2tf(v.x), f2tf(v.y), f2tf(v.z), f2tf(v.w));
    }
    __syncthreads();

    uint32_t qa[8][4];
#pragma unroll
    for (int ks = 0; ks < 8; ks++) {
        qa[ks][0] = KQ[(w16 + r) * 68 + ks * 8 + c];
        qa[ks][1] = KQ[(w16 + r + 8) * 68 + ks * 8 + c];
        qa[ks][2] = KQ[(w16 + r) * 68 + ks * 8 + c + 4];
        qa[ks][3] = KQ[(w16 + r + 8) * 68 + ks * 8 + c + 4];
    }

    float o[8][4];
#pragma unroll
    for (int nt = 0; nt < 8; nt++)
#pragma unroll
        for (int j = 0; j < 4; j++) o[nt][j] = 0.0f;
    float m0r = -INFINITY, m1r = -INFINITY, l0 = 0.0f, l1 = 0.0f;

    for (int n0 = 0; n0 < L2; n0 += 64) {
        __syncthreads();
#pragma unroll
        for (int i = 0; i < 8; i++) {
            int lin = tid + i * 128;
            int row = lin >> 4, c4 = (lin & 15) * 4;
            float4 kv = *(const float4*)(Kb + (size_t)(n0 + row) * 512 + c4);
            *(uint4*)(KQ + row * 68 + c4) =
                make_uint4(f2tf(kv.x), f2tf(kv.y), f2tf(kv.z), f2tf(kv.w));
            float4 vv = *(const float4*)(Vb + (size_t)(n0 + row) * 512 + c4);
            *(uint4*)(Vs + row * 72 + c4) =
                make_uint4(f2tf(vv.x), f2tf(vv.y), f2tf(vv.z), f2tf(vv.w));
        }
        uint32_t w00 = __ldg(pr0 + (n0 >> 5)), w01 = __ldg(pr0 + (n0 >> 5) + 1);
        uint32_t w10 = __ldg(pr1 + (n0 >> 5)), w11 = __ldg(pr1 + (n0 >> 5) + 1);
        __syncthreads();

        float s[8][4];
#pragma unroll
        for (int nt = 0; nt < 8; nt++)
#pragma unroll
            for (int j = 0; j < 4; j++) s[nt][j] = 0.0f;
#pragma unroll
        for (int ks = 0; ks < 8; ks++) {
#pragma unroll
            for (int nt = 0; nt < 8; nt++) {
                uint32_t b0 = KQ[(nt * 8 + r) * 68 + ks * 8 + c];
                uint32_t b1 = KQ[(nt * 8 + r) * 68 + ks * 8 + c + 4];
                mma8(s[nt], qa[ks], b0, b1);
            }
        }

#pragma unroll
        for (int nt = 0; nt < 8; nt++) {
            int k0 = nt * 8 + 2 * c;
            uint32_t wr0 = (k0 < 32) ? w00 : w01;
            uint32_t wr1 = (k0 < 32) ? w10 : w11;
            int sh = k0 & 31;
            s[nt][0] = ((wr0 >> sh) & 1u)       ? s[nt][0] * SCALE : NEGV;
            s[nt][1] = ((wr0 >> (sh + 1)) & 1u) ? s[nt][1] * SCALE : NEGV;
            s[nt][2] = ((wr1 >> sh) & 1u)       ? s[nt][2] * SCALE : NEGV;
            s[nt][3] = ((wr1 >> (sh + 1)) & 1u) ? s[nt][3] * SCALE : NEGV;
        }

        float tm0 = -INFINITY, tm1 = -INFINITY;
#pragma unroll
        for (int nt = 0; nt < 8; nt++) {
            tm0 = fmaxf(tm0, fmaxf(s[nt][0], s[nt][1]));
            tm1 = fmaxf(tm1, fmaxf(s[nt][2], s[nt][3]));
        }
        tm0 = fmaxf(tm0, __shfl_xor_sync(0xffffffffu, tm0, 1));
        tm0 = fmaxf(tm0, __shfl_xor_sync(0xffffffffu, tm0, 2));
        tm1 = fmaxf(tm1, __shfl_xor_sync(0xffffffffu, tm1, 1));
        tm1 = fmaxf(tm1, __shfl_xor_sync(0xffffffffu, tm1, 2));
        float mn0 = fmaxf(m0r, tm0), mn1 = fmaxf(m1r, tm1);
        float a0 = __expf(m0r - mn0), a1 = __expf(m1r - mn1);
        m0r = mn0; m1r = mn1;

        float rs0 = 0.0f, rs1 = 0.0f;
#pragma unroll
        for (int nt = 0; nt < 8; nt++) {
            float p0 = __expf(s[nt][0] - mn0);
            float p1 = __expf(s[nt][1] - mn0);
            float p2 = __expf(s[nt][2] - mn1);
            float p3 = __expf(s[nt][3] - mn1);
            rs0 += p0 + p1; rs1 += p2 + p3;
            int col = nt * 8 + 2 * c;
            Ps[(w16 + r) * 68 + col]         = f2tf(p0);
            Ps[(w16 + r) * 68 + col + 1]     = f2tf(p1);
            Ps[(w16 + r + 8) * 68 + col]     = f2tf(p2);
            Ps[(w16 + r + 8) * 68 + col + 1] = f2tf(p3);
        }
        rs0 += __shfl_xor_sync(0xffffffffu, rs0, 1);
        rs0 += __shfl_xor_sync(0xffffffffu, rs0, 2);
        rs1 += __shfl_xor_sync(0xffffffffu, rs1, 1);
        rs1 += __shfl_xor_sync(0xffffffffu, rs1, 2);
        l0 = l0 * a0 + rs0;
        l1 = l1 * a1 + rs1;
#pragma unroll
        for (int nt = 0; nt < 8; nt++) {
            o[nt][0] *= a0; o[nt][1] *= a0;
            o[nt][2] *= a1; o[nt][3] *= a1;
        }
        __syncwarp();

        uint32_t pa[8][4];
#pragma unroll
        for (int ks = 0; ks < 8; ks++) {
            pa[ks][0] = Ps[(w16 + r) * 68 + ks * 8 + c];
            pa[ks][1] = Ps[(w16 + r + 8) * 68 + ks * 8 + c];
            pa[ks][2] = Ps[(w16 + r) * 68 + ks * 8 + c + 4];
            pa[ks][3] = Ps[(w16 + r + 8) * 68 + ks * 8 + c + 4];
        }
#pragma unroll
        for (int ks = 0; ks < 8; ks++) {
#pragma unroll
            for (int nt = 0; nt < 8; nt++) {
                uint32_t b0 = Vs[(ks * 8 + c) * 72 + nt * 8 + r];
                uint32_t b1 = Vs[(ks * 8 + c + 4) * 72 + nt * 8 + r];
                mma8(o[nt], pa[ks], b0, b1);
            }
        }
    }

    float inv0 = 1.0f / l0, inv1 = 1.0f / l1;
    float* Ob = Out + ((size_t)b * L1 + q0) * 512 + h * 64;
#pragma unroll
    for (int nt = 0; nt < 8; nt++) {
        int col = nt * 8 + 2 * c;
        float2 v0, v1;
        v0.x = gelu_exact(o[nt][0] * inv0);
        v0.y = gelu_exact(o[nt][1] * inv0);
        v1.x = gelu_exact(o[nt][2] * inv1);
        v1.y = gelu_exact(o[nt][3] * inv1);
        *(float2*)(Ob + (size_t)(w16 + r) * 512 + col) = v0;
        *(float2*)(Ob + (size_t)(w16 + r + 8) * 512 + col) = v1;
    }
}

// ---------------- layernorm(E + A) -------------------------------------------
__global__ __launch_bounds__(256) void ln_residual(const float* __restrict__ E,
                                                   const float* __restrict__ A,
                                                   const float* __restrict__ g,
                                                   const float* __restrict__ bb,
                                                   float* __restrict__ Out) {
    __shared__ float s1[256], s2[256];
    int tid = threadIdx.x;
    size_t base = (size_t)blockIdx.x * 512;
    float x0 = E[base + tid] + A[base + tid];
    float x1 = E[base + tid + 256] + A[base + tid + 256];
    s1[tid] = x0 + x1;
    s2[tid] = x0 * x0 + x1 * x1;
    __syncthreads();
    for (int s = 128; s > 0; s >>= 1) {
        if (tid < s) { s1[tid] += s1[tid + s]; s2[tid] += s2[tid + s]; }
        __syncthreads();
    }
    float mu  = s1[0] * (1.0f / 512.0f);
    float var = s2[0] * (1.0f / 512.0f) - mu * mu;
    float inv = rsqrtf(var + 1e-7f);
    Out[base + tid]       = (x0 - mu) * inv * g[tid]       + bb[tid];
    Out[base + tid + 256] = (x1 - mu) * inv * g[tid + 256] + bb[tid + 256];
}

// =============================================================================
extern "C" void kernel_launch(void* const* d_in, const int* in_sizes, int n_in,
                              void* d_out, int out_size) {
    const float* X    = (const float*)d_in[0];
    const int*   inc  = (const int*)d_in[1];
    const float* E    = (const float*)d_in[3];
    const float* Wqn  = (const float*)d_in[4];   const float* bqn = (const float*)d_in[5];
    const float* Wkn  = (const float*)d_in[6];   const float* bkn = (const float*)d_in[7];
    const float* Wvn  = (const float*)d_in[8];   const float* bvn = (const float*)d_in[9];
    const float* Wqe  = (const float*)d_in[10];  const float* bqe = (const float*)d_in[11];
    const float* Wke  = (const float*)d_in[12];  const float* bke = (const float*)d_in[13];
    const float* Wve  = (const float*)d_in[14];  const float* bve = (const float*)d_in[15];
    const float* Wm1  = (const float*)d_in[16];  const float* bm1 = (const float*)d_in[17];
    const float* Wm2  = (const float*)d_in[18];  const float* bm2 = (const float*)d_in[19];
    const float* g_ln = (const float*)d_in[20];  const float* b_ln = (const float*)d_in[21];

    float* out  = (float*)d_out;
    float* Xout = out;                              // [B,N,512]
    float* Eout = out + (size_t)Bc * Nn * Dd;       // [B,M,512]

    float* sc = nullptr;
    cudaGetSymbolAddress((void**)&sc, g_scratch);
    float* Qn    = sc + OFF_QN;
    float* Kn    = sc + OFF_KN;
    float* Vn    = sc + OFF_VN;
    float* Qe    = sc + OFF_QE;
    float* Ke    = sc + OFF_KE;
    float* Ve    = sc + OFF_VE;
    float* Eattn = sc + OFF_EATTN;
    float* Eln   = sc + OFF_ELN;
    float* Hid   = sc + OFF_HID;
    uint32_t* pkO = (uint32_t*)(sc + OFF_PKO);
    uint32_t* pkT = (uint32_t*)(sc + OFF_PKT);

    static int smem_set = 0;
    if (!smem_set) {
        cudaFuncSetAttribute(flash_tc, cudaFuncAttributeMaxDynamicSharedMemorySize,
                             FLASH_SMEM);
        smem_set = 1;
    }

    // bit-pack masks (both orientations)
    pack_mask<<<(Bc * Nn * (Mm / 32)) / 256, 256>>>(inc, pkO);
    pack_maskT<<<dim3(Nn / 32, Mm / 32, Bc), dim3(32, 8)>>>(inc, pkT);

    // projections (block 128x128)
    sgemm_tc<<<dim3(4, (Bc * Nn) / 128), 256>>>(X, Wqn, bqn, Qn, 0);
    sgemm_tc<<<dim3(4, (Bc * Nn) / 128), 256>>>(X, Wkn, bkn, Kn, 0);
    sgemm_tc<<<dim3(4, (Bc * Nn) / 128), 256>>>(X, Wvn, bvn, Vn, 0);
    sgemm_tc<<<dim3(4, (Bc * Mm) / 128), 256>>>(E, Wqe, bqe, Qe, 0);

    // stage 1: edges attend over nodes
    flash_tc<<<dim3(Mm / 64, Bc * Hh), 128, FLASH_SMEM>>>(Qe, Kn, Vn, pkT, Eattn,
                                                          Mm, Nn);

    // residual layernorm + MLP -> E_ (into d_out tail)
    ln_residual<<<Bc * Mm, 256>>>(E, Eattn, g_ln, b_ln, Eln);
    sgemm_tc<<<dim3(4, (Bc * Mm) / 128), 256>>>(Eln, Wm1, bm1, Hid, 1);
    sgemm_tc<<<dim3(4, (Bc * Mm) / 128), 256>>>(Hid, Wm2, bm2, Eout, 0);

    // edge K/V projections from final E_
    sgemm_tc<<<dim3(4, (Bc * Mm) / 128), 256>>>(Eout, Wke, bke, Ke, 0);
    sgemm_tc<<<dim3(4, (Bc * Mm) / 128), 256>>>(Eout, Wve, bve, Ve, 0);

    // stage 2: nodes attend over edges
    flash_tc<<<dim3(Nn / 64, Bc * Hh), 128, FLASH_SMEM>>>(Qn, Ke, Ve, pkO, Xout,
                                                          Nn, Mm);
}

// round 5
// speedup vs baseline: 4.3667x; 1.1615x over previous
#include <cuda_runtime.h>
#include <cuda_bf16.h>
#include <math.h>
#include <stdint.h>

#define Bc 4
#define Nn 2048
#define Mm 1024
#define Dd 512
#define Hh 8
#define SCALE 0.125f
#define NEGV -9e15f

// ---------------- scratch (static device memory; no allocations) ------------
#define OFF_QN    0ULL
#define OFF_KN    4194304ULL
#define OFF_VN    8388608ULL
#define OFF_QE    12582912ULL
#define OFF_KE    14680064ULL
#define OFF_VE    16777216ULL
#define OFF_EATTN 18874368ULL
#define OFF_ELN   20971520ULL
#define OFF_HID   23068672ULL
#define OFF_PKO   25165824ULL   /* 262144 u32 : [B][N][M/32]  */
#define OFF_PKT   25427968ULL   /* 262144 u32 : [B][M][N/32]  */
#define SCRATCH_FLOATS 25690112ULL

__device__ float g_scratch[SCRATCH_FLOATS];

__device__ __forceinline__ float gelu_exact(float x) {
    return 0.5f * x * (1.0f + erff(x * 0.70710678118654752f));
}

__device__ __forceinline__ uint32_t f2tf(float x) {
    uint32_t u;
    asm("cvt.rna.tf32.f32 %0, %1;" : "=r"(u) : "f"(x));
    return u;
}

__device__ __forceinline__ void mma8(float d[4], const uint32_t a[4],
                                     uint32_t b0, uint32_t b1) {
    asm volatile("mma.sync.aligned.m16n8k8.row.col.f32.tf32.tf32.f32 "
                 "{%0,%1,%2,%3}, {%4,%5,%6,%7}, {%8,%9}, {%0,%1,%2,%3};"
                 : "+f"(d[0]), "+f"(d[1]), "+f"(d[2]), "+f"(d[3])
                 : "r"(a[0]), "r"(a[1]), "r"(a[2]), "r"(a[3]),
                   "r"(b0), "r"(b1));
}

// ---------------- bit-pack masks ---------------------------------------------
__global__ __launch_bounds__(256) void pack_mask(const int* __restrict__ inc,
                                                 uint32_t* __restrict__ pk) {
    int w = blockIdx.x * 256 + threadIdx.x;
    int row = w >> 5, mw = w & 31;
    const int4* p = (const int4*)(inc + (size_t)row * Mm + mw * 32);
    uint32_t v = 0;
#pragma unroll
    for (int i = 0; i < 8; i++) {
        int4 q = p[i];
        v |= (q.x > 0 ? 1u : 0u) << (i * 4 + 0);
        v |= (q.y > 0 ? 1u : 0u) << (i * 4 + 1);
        v |= (q.z > 0 ? 1u : 0u) << (i * 4 + 2);
        v |= (q.w > 0 ? 1u : 0u) << (i * 4 + 3);
    }
    pk[w] = v;
}

__global__ void pack_maskT(const int* __restrict__ inc,
                           uint32_t* __restrict__ pk) {
    __shared__ int t[32][33];
    int b  = blockIdx.z;
    int n0 = blockIdx.x * 32;
    int m0 = blockIdx.y * 32;
    int tx = threadIdx.x, ty = threadIdx.y;
    for (int i = ty; i < 32; i += 8)
        t[i][tx] = inc[((size_t)b * Nn + n0 + i) * Mm + m0 + tx];
    __syncthreads();
    if (ty == 0) {
        uint32_t v = 0;
#pragma unroll
        for (int i = 0; i < 32; i++)
            v |= (t[i][tx] > 0 ? 1u : 0u) << i;
        pk[((size_t)b * Mm + m0 + tx) * (Nn / 32) + (n0 >> 5)] = v;
    }
}

// ---------------- tf32 tensor-core SGEMM -------------------------------------
// block 128x128, 8 warps in 4x2, warp tile 32x64
__global__ __launch_bounds__(256) void sgemm_tc(const float* __restrict__ A,
                                                const float* __restrict__ W,
                                                const float* __restrict__ bias,
                                                float* __restrict__ C,
                                                int act) {
    __shared__ uint32_t As[128][36];
    __shared__ uint32_t Ws[32][136];
    int tid = threadIdx.x;
    int w = tid >> 5, lane = tid & 31;
    int r = lane >> 2, c = lane & 3;
    int wm = (w & 3) * 32;
    int wn = (w >> 2) * 64;
    int row0 = blockIdx.y * 128, col0 = blockIdx.x * 128;

    float acc[2][8][4];
#pragma unroll
    for (int mi = 0; mi < 2; mi++)
#pragma unroll
        for (int nt = 0; nt < 8; nt++)
#pragma unroll
            for (int j = 0; j < 4; j++) acc[mi][nt][j] = 0.0f;

    for (int kt = 0; kt < 512; kt += 32) {
        __syncthreads();
#pragma unroll
        for (int i = 0; i < 4; i++) {
            int lin = tid + i * 256;
            int m = lin >> 3, k4 = (lin & 7) * 4;
            float4 v = *(const float4*)&A[(size_t)(row0 + m) * 512 + kt + k4];
            *(uint4*)&As[m][k4] = make_uint4(f2tf(v.x), f2tf(v.y), f2tf(v.z), f2tf(v.w));
        }
#pragma unroll
        for (int i = 0; i < 4; i++) {
            int lin = tid + i * 256;
            int k = lin >> 5, n4 = (lin & 31) * 4;
            float4 v = *(const float4*)&W[(size_t)(kt + k) * 512 + col0 + n4];
            *(uint4*)&Ws[k][n4] = make_uint4(f2tf(v.x), f2tf(v.y), f2tf(v.z), f2tf(v.w));
        }
        __syncthreads();
#pragma unroll
        for (int ks = 0; ks < 4; ks++) {
            uint32_t a[2][4];
#pragma unroll
            for (int mi = 0; mi < 2; mi++) {
                int mr = wm + mi * 16;
                a[mi][0] = As[mr + r][ks * 8 + c];
                a[mi][1] = As[mr + r + 8][ks * 8 + c];
                a[mi][2] = As[mr + r][ks * 8 + c + 4];
                a[mi][3] = As[mr + r + 8][ks * 8 + c + 4];
            }
#pragma unroll
            for (int nt = 0; nt < 8; nt++) {
                uint32_t b0 = Ws[ks * 8 + c][wn + nt * 8 + r];
                uint32_t b1 = Ws[ks * 8 + c + 4][wn + nt * 8 + r];
                mma8(acc[0][nt], a[0], b0, b1);
                mma8(acc[1][nt], a[1], b0, b1);
            }
        }
    }
#pragma unroll
    for (int mi = 0; mi < 2; mi++) {
        int row = row0 + wm + mi * 16 + r;
#pragma unroll
        for (int nt = 0; nt < 8; nt++) {
            int col = col0 + wn + nt * 8 + 2 * c;
            float2 bv = *(const float2*)&bias[col];
            float2 v0, v1;
            v0.x = acc[mi][nt][0] + bv.x; v0.y = acc[mi][nt][1] + bv.y;
            v1.x = acc[mi][nt][2] + bv.x; v1.y = acc[mi][nt][3] + bv.y;
            if (act) {
                v0.x = gelu_exact(v0.x); v0.y = gelu_exact(v0.y);
                v1.x = gelu_exact(v1.x); v1.y = gelu_exact(v1.y);
            }
            *(float2*)&C[(size_t)row * 512 + col] = v0;
            *(float2*)&C[(size_t)(row + 8) * 512 + col] = v1;
        }
    }
}

// ---------------- tf32 tensor-core flash attention v2 ------------------------
// 128 threads (4 warps). Q tile 128 rows; warp owns 32 rows (mi=2 subtiles).
// K/V fragments reused across both m-subtiles -> half the LDS bytes per row.
#define FLASH_SMEM ((64 * 68 + 64 * 72 + 128 * 68) * 4)

__global__ __launch_bounds__(128) void flash_tc(const float* __restrict__ Q,
                                                const float* __restrict__ K,
                                                const float* __restrict__ V,
                                                const uint32_t* __restrict__ pk,
                                                float* __restrict__ Out,
                                                int L1, int L2) {
    extern __shared__ uint32_t fsm[];
    uint32_t* KQ = fsm;                        // K tile  [64][68]
    uint32_t* Vs = fsm + 64 * 68;              // V tile  [64][72] (transposed-ish use)
    uint32_t* Ps = fsm + 64 * 68 + 64 * 72;    // Q stage / P tile [128][68]

    int tid = threadIdx.x;
    int w = tid >> 5, lane = tid & 31;
    int r = lane >> 2, c = lane & 3;
    int w32 = w * 32;
    int bh = blockIdx.y;
    int b = bh >> 3, h = bh & 7;
    int q0 = blockIdx.x * 128;

    const float* Qb = Q + ((size_t)b * L1 + q0) * 512 + h * 64;
    const float* Kb = K + ((size_t)b * L2) * 512 + h * 64;
    const float* Vb = V + ((size_t)b * L2) * 512 + h * 64;
    int nw = L2 >> 5;
    const uint32_t* pr[2][2];
#pragma unroll
    for (int mi = 0; mi < 2; mi++) {
        pr[mi][0] = pk + ((size_t)b * L1 + q0 + w32 + mi * 16 + r) * nw;
        pr[mi][1] = pk + ((size_t)b * L1 + q0 + w32 + mi * 16 + r + 8) * nw;
    }

    // stage Q (128 rows) into Ps, then load Q fragments to registers
#pragma unroll
    for (int i = 0; i < 16; i++) {
        int lin = tid + i * 128;
        int row = lin >> 4, c4 = (lin & 15) * 4;
        float4 v = *(const float4*)(Qb + (size_t)row * 512 + c4);
        *(uint4*)(Ps + row * 68 + c4) = make_uint4(f2tf(v.x), f2tf(v.y), f2tf(v.z), f2tf(v.w));
    }
    __syncthreads();

    uint32_t qa[2][8][4];
#pragma unroll
    for (int mi = 0; mi < 2; mi++) {
        int mr = w32 + mi * 16;
#pragma unroll
        for (int ks = 0; ks < 8; ks++) {
            qa[mi][ks][0] = Ps[(mr + r) * 68 + ks * 8 + c];
            qa[mi][ks][1] = Ps[(mr + r + 8) * 68 + ks * 8 + c];
            qa[mi][ks][2] = Ps[(mr + r) * 68 + ks * 8 + c + 4];
            qa[mi][ks][3] = Ps[(mr + r + 8) * 68 + ks * 8 + c + 4];
        }
    }

    float o[2][8][4];
#pragma unroll
    for (int mi = 0; mi < 2; mi++)
#pragma unroll
        for (int nt = 0; nt < 8; nt++)
#pragma unroll
            for (int j = 0; j < 4; j++) o[mi][nt][j] = 0.0f;
    float mrow[2][2], lrow[2][2];
#pragma unroll
    for (int mi = 0; mi < 2; mi++) {
        mrow[mi][0] = -INFINITY; mrow[mi][1] = -INFINITY;
        lrow[mi][0] = 0.0f; lrow[mi][1] = 0.0f;
    }

    for (int n0 = 0; n0 < L2; n0 += 64) {
        __syncthreads();
        // stage K and V tiles (64 rows each)
#pragma unroll
        for (int i = 0; i < 8; i++) {
            int lin = tid + i * 128;
            int row = lin >> 4, c4 = (lin & 15) * 4;
            float4 kv = *(const float4*)(Kb + (size_t)(n0 + row) * 512 + c4);
            *(uint4*)(KQ + row * 68 + c4) =
                make_uint4(f2tf(kv.x), f2tf(kv.y), f2tf(kv.z), f2tf(kv.w));
            float4 vv = *(const float4*)(Vb + (size_t)(n0 + row) * 512 + c4);
            *(uint4*)(Vs + row * 72 + c4) =
                make_uint4(f2tf(vv.x), f2tf(vv.y), f2tf(vv.z), f2tf(vv.w));
        }
        uint32_t mw[2][2][2];
#pragma unroll
        for (int mi = 0; mi < 2; mi++)
#pragma unroll
            for (int hf = 0; hf < 2; hf++) {
                mw[mi][hf][0] = __ldg(pr[mi][hf] + (n0 >> 5));
                mw[mi][hf][1] = __ldg(pr[mi][hf] + (n0 >> 5) + 1);
            }
        __syncthreads();

        // S = Q @ K^T  (K-frags shared across both m-subtiles)
        float s[2][8][4];
#pragma unroll
        for (int mi = 0; mi < 2; mi++)
#pragma unroll
            for (int nt = 0; nt < 8; nt++)
#pragma unroll
                for (int j = 0; j < 4; j++) s[mi][nt][j] = 0.0f;
#pragma unroll
        for (int ks = 0; ks < 8; ks++) {
#pragma unroll
            for (int nt = 0; nt < 8; nt++) {
                uint32_t b0 = KQ[(nt * 8 + r) * 68 + ks * 8 + c];
                uint32_t b1 = KQ[(nt * 8 + r) * 68 + ks * 8 + c + 4];
                mma8(s[0][nt], qa[0][ks], b0, b1);
                mma8(s[1][nt], qa[1][ks], b0, b1);
            }
        }

        // mask + scale + online softmax per m-subtile
#pragma unroll
        for (int mi = 0; mi < 2; mi++) {
#pragma unroll
            for (int nt = 0; nt < 8; nt++) {
                int k0 = nt * 8 + 2 * c;
                uint32_t wr0 = (k0 < 32) ? mw[mi][0][0] : mw[mi][0][1];
                uint32_t wr1 = (k0 < 32) ? mw[mi][1][0] : mw[mi][1][1];
                int sh = k0 & 31;
                s[mi][nt][0] = ((wr0 >> sh) & 1u)       ? s[mi][nt][0] * SCALE : NEGV;
                s[mi][nt][1] = ((wr0 >> (sh + 1)) & 1u) ? s[mi][nt][1] * SCALE : NEGV;
                s[mi][nt][2] = ((wr1 >> sh) & 1u)       ? s[mi][nt][2] * SCALE : NEGV;
                s[mi][nt][3] = ((wr1 >> (sh + 1)) & 1u) ? s[mi][nt][3] * SCALE : NEGV;
            }

            float tm0 = -INFINITY, tm1 = -INFINITY;
#pragma unroll
            for (int nt = 0; nt < 8; nt++) {
                tm0 = fmaxf(tm0, fmaxf(s[mi][nt][0], s[mi][nt][1]));
                tm1 = fmaxf(tm1, fmaxf(s[mi][nt][2], s[mi][nt][3]));
            }
            tm0 = fmaxf(tm0, __shfl_xor_sync(0xffffffffu, tm0, 1));
            tm0 = fmaxf(tm0, __shfl_xor_sync(0xffffffffu, tm0, 2));
            tm1 = fmaxf(tm1, __shfl_xor_sync(0xffffffffu, tm1, 1));
            tm1 = fmaxf(tm1, __shfl_xor_sync(0xffffffffu, tm1, 2));
            float mn0 = fmaxf(mrow[mi][0], tm0), mn1 = fmaxf(mrow[mi][1], tm1);
            float a0 = __expf(mrow[mi][0] - mn0), a1 = __expf(mrow[mi][1] - mn1);
            mrow[mi][0] = mn0; mrow[mi][1] = mn1;

            float rs0 = 0.0f, rs1 = 0.0f;
            int mr = w32 + mi * 16;
#pragma unroll
            for (int nt = 0; nt < 8; nt++) {
                float p0 = __expf(s[mi][nt][0] - mn0);
                float p1 = __expf(s[mi][nt][1] - mn0);
                float p2 = __expf(s[mi][nt][2] - mn1);
                float p3 = __expf(s[mi][nt][3] - mn1);
                rs0 += p0 + p1; rs1 += p2 + p3;
                int col = nt * 8 + 2 * c;
                Ps[(mr + r) * 68 + col]         = f2tf(p0);
                Ps[(mr + r) * 68 + col + 1]     = f2tf(p1);
                Ps[(mr + r + 8) * 68 + col]     = f2tf(p2);
                Ps[(mr + r + 8) * 68 + col + 1] = f2tf(p3);
            }
            rs0 += __shfl_xor_sync(0xffffffffu, rs0, 1);
            rs0 += __shfl_xor_sync(0xffffffffu, rs0, 2);
            rs1 += __shfl_xor_sync(0xffffffffu, rs1, 1);
            rs1 += __shfl_xor_sync(0xffffffffu, rs1, 2);
            lrow[mi][0] = lrow[mi][0] * a0 + rs0;
            lrow[mi][1] = lrow[mi][1] * a1 + rs1;
#pragma unroll
            for (int nt = 0; nt < 8; nt++) {
                o[mi][nt][0] *= a0; o[mi][nt][1] *= a0;
                o[mi][nt][2] *= a1; o[mi][nt][3] *= a1;
            }
        }
        __syncwarp();

        // O += P @ V  (V-frags shared across both m-subtiles)
        uint32_t pa[2][4];
#pragma unroll
        for (int ks = 0; ks < 8; ks++) {
#pragma unroll
            for (int mi = 0; mi < 2; mi++) {
                int mr = w32 + mi * 16;
                pa[mi][0] = Ps[(mr + r) * 68 + ks * 8 + c];
                pa[mi][1] = Ps[(mr + r + 8) * 68 + ks * 8 + c];
                pa[mi][2] = Ps[(mr + r) * 68 + ks * 8 + c + 4];
                pa[mi][3] = Ps[(mr + r + 8) * 68 + ks * 8 + c + 4];
            }
#pragma unroll
            for (int nt = 0; nt < 8; nt++) {
                uint32_t b0 = Vs[(ks * 8 + c) * 72 + nt * 8 + r];
                uint32_t b1 = Vs[(ks * 8 + c + 4) * 72 + nt * 8 + r];
                mma8(o[0][nt], pa[0], b0, b1);
                mma8(o[1][nt], pa[1], b0, b1);
            }
        }
    }

    // epilogue
    float* Ob = Out + ((size_t)b * L1 + q0) * 512 + h * 64;
#pragma unroll
    for (int mi = 0; mi < 2; mi++) {
        float inv0 = 1.0f / lrow[mi][0], inv1 = 1.0f / lrow[mi][1];
        int mr = w32 + mi * 16;
#pragma unroll
        for (int nt = 0; nt < 8; nt++) {
            int col = nt * 8 + 2 * c;
            float2 v0, v1;
            v0.x = gelu_exact(o[mi][nt][0] * inv0);
            v0.y = gelu_exact(o[mi][nt][1] * inv0);
            v1.x = gelu_exact(o[mi][nt][2] * inv1);
            v1.y = gelu_exact(o[mi][nt][3] * inv1);
            *(float2*)(Ob + (size_t)(mr + r) * 512 + col) = v0;
            *(float2*)(Ob + (size_t)(mr + r + 8) * 512 + col) = v1;
        }
    }
}

// ---------------- layernorm(E + A) -------------------------------------------
__global__ __launch_bounds__(256) void ln_residual(const float* __restrict__ E,
                                                   const float* __restrict__ A,
                                                   const float* __restrict__ g,
                                                   const float* __restrict__ bb,
                                                   float* __restrict__ Out) {
    __shared__ float s1[256], s2[256];
    int tid = threadIdx.x;
    size_t base = (size_t)blockIdx.x * 512;
    float x0 = E[base + tid] + A[base + tid];
    float x1 = E[base + tid + 256] + A[base + tid + 256];
    s1[tid] = x0 + x1;
    s2[tid] = x0 * x0 + x1 * x1;
    __syncthreads();
    for (int s = 128; s > 0; s >>= 1) {
        if (tid < s) { s1[tid] += s1[tid + s]; s2[tid] += s2[tid + s]; }
        __syncthreads();
    }
    float mu  = s1[0] * (1.0f / 512.0f);
    float var = s2[0] * (1.0f / 512.0f) - mu * mu;
    float inv = rsqrtf(var + 1e-7f);
    Out[base + tid]       = (x0 - mu) * inv * g[tid]       + bb[tid];
    Out[base + tid + 256] = (x1 - mu) * inv * g[tid + 256] + bb[tid + 256];
}

// =============================================================================
extern "C" void kernel_launch(void* const* d_in, const int* in_sizes, int n_in,
                              void* d_out, int out_size) {
    const float* X    = (const float*)d_in[0];
    const int*   inc  = (const int*)d_in[1];
    const float* E    = (const float*)d_in[3];
    const float* Wqn  = (const float*)d_in[4];   const float* bqn = (const float*)d_in[5];
    const float* Wkn  = (const float*)d_in[6];   const float* bkn = (const float*)d_in[7];
    const float* Wvn  = (const float*)d_in[8];   const float* bvn = (const float*)d_in[9];
    const float* Wqe  = (const float*)d_in[10];  const float* bqe = (const float*)d_in[11];
    const float* Wke  = (const float*)d_in[12];  const float* bke = (const float*)d_in[13];
    const float* Wve  = (const float*)d_in[14];  const float* bve = (const float*)d_in[15];
    const float* Wm1  = (const float*)d_in[16];  const float* bm1 = (const float*)d_in[17];
    const float* Wm2  = (const float*)d_in[18];  const float* bm2 = (const float*)d_in[19];
    const float* g_ln = (const float*)d_in[20];  const float* b_ln = (const float*)d_in[21];

    float* out  = (float*)d_out;
    float* Xout = out;                              // [B,N,512]
    float* Eout = out + (size_t)Bc * Nn * Dd;       // [B,M,512]

    float* sc = nullptr;
    cudaGetSymbolAddress((void**)&sc, g_scratch);
    float* Qn    = sc + OFF_QN;
    float* Kn    = sc + OFF_KN;
    float* Vn    = sc + OFF_VN;
    float* Qe    = sc + OFF_QE;
    float* Ke    = sc + OFF_KE;
    float* Ve    = sc + OFF_VE;
    float* Eattn = sc + OFF_EATTN;
    float* Eln   = sc + OFF_ELN;
    float* Hid   = sc + OFF_HID;
    uint32_t* pkO = (uint32_t*)(sc + OFF_PKO);
    uint32_t* pkT = (uint32_t*)(sc + OFF_PKT);

    static int smem_set = 0;
    if (!smem_set) {
        cudaFuncSetAttribute(flash_tc, cudaFuncAttributeMaxDynamicSharedMemorySize,
                             FLASH_SMEM);
        smem_set = 1;
    }

    // bit-pack masks (both orientations)
    pack_mask<<<(Bc * Nn * (Mm / 32)) / 256, 256>>>(inc, pkO);
    pack_maskT<<<dim3(Nn / 32, Mm / 32, Bc), dim3(32, 8)>>>(inc, pkT);

    // projections (block 128x128)
    sgemm_tc<<<dim3(4, (Bc * Nn) / 128), 256>>>(X, Wqn, bqn, Qn, 0);
    sgemm_tc<<<dim3(4, (Bc * Nn) / 128), 256>>>(X, Wkn, bkn, Kn, 0);
    sgemm_tc<<<dim3(4, (Bc * Nn) / 128), 256>>>(X, Wvn, bvn, Vn, 0);
    sgemm_tc<<<dim3(4, (Bc * Mm) / 128), 256>>>(E, Wqe, bqe, Qe, 0);

    // stage 1: edges attend over nodes (Q tile 128)
    flash_tc<<<dim3(Mm / 128, Bc * Hh), 128, FLASH_SMEM>>>(Qe, Kn, Vn, pkT, Eattn,
                                                           Mm, Nn);

    // residual layernorm + MLP -> E_ (into d_out tail)
    ln_residual<<<Bc * Mm, 256>>>(E, Eattn, g_ln, b_ln, Eln);
    sgemm_tc<<<dim3(4, (Bc * Mm) / 128), 256>>>(Eln, Wm1, bm1, Hid, 1);
    sgemm_tc<<<dim3(4, (Bc * Mm) / 128), 256>>>(Hid, Wm2, bm2, Eout, 0);

    // edge K/V projections from final E_
    sgemm_tc<<<dim3(4, (Bc * Mm) / 128), 256>>>(Eout, Wke, bke, Ke, 0);
    sgemm_tc<<<dim3(4, (Bc * Mm) / 128), 256>>>(Eout, Wve, bve, Ve, 0);

    // stage 2: nodes attend over edges (Q tile 128)
    flash_tc<<<dim3(Nn / 128, Bc * Hh), 128, FLASH_SMEM>>>(Qn, Ke, Ve, pkO, Xout,
                                                           Nn, Mm);
}

// round 6
// speedup vs baseline: 4.7528x; 1.0884x over previous
#include <cuda_runtime.h>
#include <cuda_bf16.h>
#include <math.h>
#include <stdint.h>

#define Bc 4
#define Nn 2048
#define Mm 1024
#define Dd 512
#define Hh 8
#define SCALE 0.125f
#define NEGV -9e15f

// ---------------- scratch (static device memory; no allocations) ------------
#define OFF_QN    0ULL          /* tf32 bits */
#define OFF_KN    4194304ULL
#define OFF_VN    8388608ULL
#define OFF_QE    12582912ULL
#define OFF_KE    14680064ULL
#define OFF_VE    16777216ULL
#define OFF_EATTN 18874368ULL   /* fp32 */
#define OFF_ELN   20971520ULL   /* tf32 */
#define OFF_HID   23068672ULL   /* tf32 */
#define OFF_PKO   25165824ULL
#define OFF_PKT   25427968ULL
#define OFF_XC    25690112ULL   /* tf32 copy of X : 4194304 */
#define OFF_EC    29884416ULL   /* tf32 copy of E : 2097152 */
#define OFF_WC    31981568ULL   /* tf32 weights 8 x 262144  */
#define OFF_EOUTC 34078720ULL   /* tf32 copy of Eout : 2097152 */
#define SCRATCH_FLOATS 36175872ULL

__device__ float g_scratch[SCRATCH_FLOATS];

__device__ __forceinline__ float gelu_exact(float x) {
    return 0.5f * x * (1.0f + erff(x * 0.70710678118654752f));
}

__device__ __forceinline__ uint32_t f2tf(float x) {
    uint32_t u;
    asm("cvt.rna.tf32.f32 %0, %1;" : "=r"(u) : "f"(x));
    return u;
}

__device__ __forceinline__ void mma8(float d[4], const uint32_t a[4],
                                     uint32_t b0, uint32_t b1) {
    asm volatile("mma.sync.aligned.m16n8k8.row.col.f32.tf32.tf32.f32 "
                 "{%0,%1,%2,%3}, {%4,%5,%6,%7}, {%8,%9}, {%0,%1,%2,%3};"
                 : "+f"(d[0]), "+f"(d[1]), "+f"(d[2]), "+f"(d[3])
                 : "r"(a[0]), "r"(a[1]), "r"(a[2]), "r"(a[3]),
                   "r"(b0), "r"(b1));
}

__device__ __forceinline__ void cp16(uint32_t dst, const void* src) {
    asm volatile("cp.async.cg.shared.global [%0], [%1], 16;" :: "r"(dst), "l"(src));
}
#define CP_COMMIT() asm volatile("cp.async.commit_group;")
#define CP_WAIT(n)  asm volatile("cp.async.wait_group %0;" :: "n"(n))

// ---------------- tf32 pre-conversion ----------------------------------------
__global__ __launch_bounds__(256) void conv_tf32(const float4* __restrict__ in,
                                                 uint4* __restrict__ out, int n4) {
    int i = blockIdx.x * 256 + threadIdx.x;
    if (i < n4) {
        float4 v = in[i];
        out[i] = make_uint4(f2tf(v.x), f2tf(v.y), f2tf(v.z), f2tf(v.w));
    }
}

struct P8 { const float* p[8]; };
__global__ __launch_bounds__(256) void conv_w(P8 ws, uint32_t* __restrict__ out) {
    int g = blockIdx.y;
    int i = blockIdx.x * 256 + threadIdx.x;   // 65536 float4 per matrix
    float4 v = ((const float4*)ws.p[g])[i];
    ((uint4*)(out + (size_t)g * 262144))[i] =
        make_uint4(f2tf(v.x), f2tf(v.y), f2tf(v.z), f2tf(v.w));
}

// ---------------- bit-pack masks ---------------------------------------------
__global__ __launch_bounds__(256) void pack_mask(const int* __restrict__ inc,
                                                 uint32_t* __restrict__ pk) {
    int w = blockIdx.x * 256 + threadIdx.x;
    int row = w >> 5, mw = w & 31;
    const int4* p = (const int4*)(inc + (size_t)row * Mm + mw * 32);
    uint32_t v = 0;
#pragma unroll
    for (int i = 0; i < 8; i++) {
        int4 q = p[i];
        v |= (q.x > 0 ? 1u : 0u) << (i * 4 + 0);
        v |= (q.y > 0 ? 1u : 0u) << (i * 4 + 1);
        v |= (q.z > 0 ? 1u : 0u) << (i * 4 + 2);
        v |= (q.w > 0 ? 1u : 0u) << (i * 4 + 3);
    }
    pk[w] = v;
}

__global__ void pack_maskT(const int* __restrict__ inc,
                           uint32_t* __restrict__ pk) {
    __shared__ int t[32][33];
    int b  = blockIdx.z;
    int n0 = blockIdx.x * 32;
    int m0 = blockIdx.y * 32;
    int tx = threadIdx.x, ty = threadIdx.y;
    for (int i = ty; i < 32; i += 8)
        t[i][tx] = inc[((size_t)b * Nn + n0 + i) * Mm + m0 + tx];
    __syncthreads();
    if (ty == 0) {
        uint32_t v = 0;
#pragma unroll
        for (int i = 0; i < 32; i++)
            v |= (t[i][tx] > 0 ? 1u : 0u) << i;
        pk[((size_t)b * Mm + m0 + tx) * (Nn / 32) + (n0 >> 5)] = v;
    }
}

// ---------------- tf32 SGEMM with cp.async 2-stage pipeline -------------------
// block 128x128, 8 warps 4x2, warp tile 32x64. A, W are pre-converted tf32 bits.
struct GemmJob {
    const uint32_t* W;
    const float*    bias;
    float*          C;     // fp32 out (mode 0/2)
    uint32_t*       Cc;    // tf32 out (mode 1/2)
    int act;
    int mode;              // 0 fp32, 1 tf32, 2 both
};
struct GemmJobs { GemmJob j[3]; };

#define GEMM_SMEM ((2 * 128 * 36 + 2 * 32 * 136) * 4)

__global__ __launch_bounds__(256) void sgemm_tc(const uint32_t* __restrict__ A,
                                                GemmJobs jobs) {
    extern __shared__ uint32_t sm[];
    uint32_t* As = sm;                    // [2][128][36]
    uint32_t* Ws = sm + 2 * 128 * 36;     // [2][32][136]
    uint32_t asAddr = (uint32_t)__cvta_generic_to_shared(As);
    uint32_t wsAddr = (uint32_t)__cvta_generic_to_shared(Ws);

    const GemmJob J = jobs.j[blockIdx.z];
    int tid = threadIdx.x;
    int w = tid >> 5, lane = tid & 31;
    int r = lane >> 2, c = lane & 3;
    int wm = (w & 3) * 32;
    int wn = (w >> 2) * 64;
    int row0 = blockIdx.y * 128, col0 = blockIdx.x * 128;

    float acc[2][8][4];
#pragma unroll
    for (int mi = 0; mi < 2; mi++)
#pragma unroll
        for (int nt = 0; nt < 8; nt++)
#pragma unroll
            for (int j = 0; j < 4; j++) acc[mi][nt][j] = 0.0f;

    auto stage = [&](int buf, int kt) {
#pragma unroll
        for (int i = 0; i < 4; i++) {
            int lin = tid + i * 256;
            int m = lin >> 3, seg = lin & 7;
            cp16(asAddr + (((buf * 128 + m) * 36 + seg * 4) << 2),
                 A + (size_t)(row0 + m) * 512 + kt + seg * 4);
        }
#pragma unroll
        for (int i = 0; i < 4; i++) {
            int lin = tid + i * 256;
            int k = lin >> 5, seg = lin & 31;
            cp16(wsAddr + (((buf * 32 + k) * 136 + seg * 4) << 2),
                 J.W + (size_t)(kt + k) * 512 + col0 + seg * 4);
        }
    };

    stage(0, 0);
    CP_COMMIT();

    for (int kc = 0; kc < 16; kc++) {
        if (kc + 1 < 16) {
            stage((kc + 1) & 1, (kc + 1) * 32);
            CP_COMMIT();
            CP_WAIT(1);
        } else {
            CP_WAIT(0);
        }
        __syncthreads();
        const uint32_t* Ab = As + (kc & 1) * 128 * 36;
        const uint32_t* Wb = Ws + (kc & 1) * 32 * 136;
#pragma unroll
        for (int ks = 0; ks < 4; ks++) {
            uint32_t a[2][4];
#pragma unroll
            for (int mi = 0; mi < 2; mi++) {
                int mr = wm + mi * 16;
                a[mi][0] = Ab[(mr + r) * 36 + ks * 8 + c];
                a[mi][1] = Ab[(mr + r + 8) * 36 + ks * 8 + c];
                a[mi][2] = Ab[(mr + r) * 36 + ks * 8 + c + 4];
                a[mi][3] = Ab[(mr + r + 8) * 36 + ks * 8 + c + 4];
            }
#pragma unroll
            for (int nt = 0; nt < 8; nt++) {
                uint32_t b0 = Wb[(ks * 8 + c) * 136 + wn + nt * 8 + r];
                uint32_t b1 = Wb[(ks * 8 + c + 4) * 136 + wn + nt * 8 + r];
                mma8(acc[0][nt], a[0], b0, b1);
                mma8(acc[1][nt], a[1], b0, b1);
            }
        }
        __syncthreads();
    }

#pragma unroll
    for (int mi = 0; mi < 2; mi++) {
        int row = row0 + wm + mi * 16 + r;
#pragma unroll
        for (int nt = 0; nt < 8; nt++) {
            int col = col0 + wn + nt * 8 + 2 * c;
            float2 bv = *(const float2*)&J.bias[col];
            float x0 = acc[mi][nt][0] + bv.x, y0 = acc[mi][nt][1] + bv.y;
            float x1 = acc[mi][nt][2] + bv.x, y1 = acc[mi][nt][3] + bv.y;
            if (J.act) {
                x0 = gelu_exact(x0); y0 = gelu_exact(y0);
                x1 = gelu_exact(x1); y1 = gelu_exact(y1);
            }
            if (J.mode != 1) {
                *(float2*)&J.C[(size_t)row * 512 + col] = make_float2(x0, y0);
                *(float2*)&J.C[(size_t)(row + 8) * 512 + col] = make_float2(x1, y1);
            }
            if (J.mode >= 1) {
                *(uint2*)&J.Cc[(size_t)row * 512 + col] = make_uint2(f2tf(x0), f2tf(y0));
                *(uint2*)&J.Cc[(size_t)(row + 8) * 512 + col] = make_uint2(f2tf(x1), f2tf(y1));
            }
        }
    }
}

// ---------------- flash attention: cp.async double-buffered K/V --------------
// 128 threads / 4 warps; Q tile 128 rows; warp owns 32 rows. Inputs tf32 bits.
#define KQ_STRIDE 4352   /* 64*68 */
#define VS_STRIDE 4608   /* 64*72 */
#define FLASH_SMEM ((2 * KQ_STRIDE + 2 * VS_STRIDE + 128 * 68) * 4)

__global__ __launch_bounds__(128) void flash_tc(const uint32_t* __restrict__ Q,
                                                const uint32_t* __restrict__ K,
                                                const uint32_t* __restrict__ V,
                                                const uint32_t* __restrict__ pk,
                                                float* __restrict__ Out,
                                                int L1, int L2) {
    extern __shared__ uint32_t fsm[];
    uint32_t* KQ = fsm;                               // [2][64][68]
    uint32_t* Vs = fsm + 2 * KQ_STRIDE;               // [2][64][72]
    uint32_t* Ps = fsm + 2 * KQ_STRIDE + 2 * VS_STRIDE;  // [128][68]
    uint32_t kqAddr = (uint32_t)__cvta_generic_to_shared(KQ);
    uint32_t vsAddr = (uint32_t)__cvta_generic_to_shared(Vs);

    int tid = threadIdx.x;
    int w = tid >> 5, lane = tid & 31;
    int r = lane >> 2, c = lane & 3;
    int w32 = w * 32;
    int bh = blockIdx.y;
    int b = bh >> 3, h = bh & 7;
    int q0 = blockIdx.x * 128;

    const uint32_t* Qb = Q + ((size_t)b * L1 + q0) * 512 + h * 64;
    const uint32_t* Kb = K + ((size_t)b * L2) * 512 + h * 64;
    const uint32_t* Vb = V + ((size_t)b * L2) * 512 + h * 64;
    int nw = L2 >> 5;
    const uint32_t* pr[2][2];
#pragma unroll
    for (int mi = 0; mi < 2; mi++) {
        pr[mi][0] = pk + ((size_t)b * L1 + q0 + w32 + mi * 16 + r) * nw;
        pr[mi][1] = pk + ((size_t)b * L1 + q0 + w32 + mi * 16 + r + 8) * nw;
    }

    auto stageKV = [&](int buf, int n0) {
#pragma unroll
        for (int i = 0; i < 8; i++) {
            int lin = tid + i * 128;
            int row = lin >> 4, seg = lin & 15;
            cp16(kqAddr + ((buf * KQ_STRIDE + row * 68 + seg * 4) << 2),
                 Kb + (size_t)(n0 + row) * 512 + seg * 4);
        }
#pragma unroll
        for (int i = 0; i < 8; i++) {
            int lin = tid + i * 128;
            int row = lin >> 4, seg = lin & 15;
            cp16(vsAddr + ((buf * VS_STRIDE + row * 72 + seg * 4) << 2),
                 Vb + (size_t)(n0 + row) * 512 + seg * 4);
        }
    };

    // stage Q (already tf32) into Ps, then fragments to registers
#pragma unroll
    for (int i = 0; i < 16; i++) {
        int lin = tid + i * 128;
        int row = lin >> 4, c4 = (lin & 15) * 4;
        *(uint4*)(Ps + row * 68 + c4) = *(const uint4*)(Qb + (size_t)row * 512 + c4);
    }
    stageKV(0, 0);
    CP_COMMIT();
    __syncthreads();

    uint32_t qa[2][8][4];
#pragma unroll
    for (int mi = 0; mi < 2; mi++) {
        int mr = w32 + mi * 16;
#pragma unroll
        for (int ks = 0; ks < 8; ks++) {
            qa[mi][ks][0] = Ps[(mr + r) * 68 + ks * 8 + c];
            qa[mi][ks][1] = Ps[(mr + r + 8) * 68 + ks * 8 + c];
            qa[mi][ks][2] = Ps[(mr + r) * 68 + ks * 8 + c + 4];
            qa[mi][ks][3] = Ps[(mr + r + 8) * 68 + ks * 8 + c + 4];
        }
    }

    float o[2][8][4];
#pragma unroll
    for (int mi = 0; mi < 2; mi++)
#pragma unroll
        for (int nt = 0; nt < 8; nt++)
#pragma unroll
            for (int j = 0; j < 4; j++) o[mi][nt][j] = 0.0f;
    float mrow[2][2], lrow[2][2];
#pragma unroll
    for (int mi = 0; mi < 2; mi++) {
        mrow[mi][0] = -INFINITY; mrow[mi][1] = -INFINITY;
        lrow[mi][0] = 0.0f; lrow[mi][1] = 0.0f;
    }

    int T = L2 >> 6;
    for (int t = 0; t < T; t++) {
        int n0 = t << 6;
        if (t + 1 < T) {
            stageKV((t + 1) & 1, n0 + 64);
            CP_COMMIT();
            CP_WAIT(1);
        } else {
            CP_WAIT(0);
        }
        uint32_t mw[2][2][2];
#pragma unroll
        for (int mi = 0; mi < 2; mi++)
#pragma unroll
            for (int hf = 0; hf < 2; hf++) {
                mw[mi][hf][0] = __ldg(pr[mi][hf] + (n0 >> 5));
                mw[mi][hf][1] = __ldg(pr[mi][hf] + (n0 >> 5) + 1);
            }
        __syncthreads();
        const uint32_t* KQb = KQ + (t & 1) * KQ_STRIDE;
        const uint32_t* Vsb = Vs + (t & 1) * VS_STRIDE;

        // S = Q @ K^T
        float s[2][8][4];
#pragma unroll
        for (int mi = 0; mi < 2; mi++)
#pragma unroll
            for (int nt = 0; nt < 8; nt++)
#pragma unroll
                for (int j = 0; j < 4; j++) s[mi][nt][j] = 0.0f;
#pragma unroll
        for (int ks = 0; ks < 8; ks++) {
#pragma unroll
            for (int nt = 0; nt < 8; nt++) {
                uint32_t b0 = KQb[(nt * 8 + r) * 68 + ks * 8 + c];
                uint32_t b1 = KQb[(nt * 8 + r) * 68 + ks * 8 + c + 4];
                mma8(s[0][nt], qa[0][ks], b0, b1);
                mma8(s[1][nt], qa[1][ks], b0, b1);
            }
        }

        // mask + scale + online softmax
#pragma unroll
        for (int mi = 0; mi < 2; mi++) {
#pragma unroll
            for (int nt = 0; nt < 8; nt++) {
                int k0 = nt * 8 + 2 * c;
                uint32_t wr0 = (k0 < 32) ? mw[mi][0][0] : mw[mi][0][1];
                uint32_t wr1 = (k0 < 32) ? mw[mi][1][0] : mw[mi][1][1];
                int sh = k0 & 31;
                s[mi][nt][0] = ((wr0 >> sh) & 1u)       ? s[mi][nt][0] * SCALE : NEGV;
                s[mi][nt][1] = ((wr0 >> (sh + 1)) & 1u) ? s[mi][nt][1] * SCALE : NEGV;
                s[mi][nt][2] = ((wr1 >> sh) & 1u)       ? s[mi][nt][2] * SCALE : NEGV;
                s[mi][nt][3] = ((wr1 >> (sh + 1)) & 1u) ? s[mi][nt][3] * SCALE : NEGV;
            }

            float tm0 = -INFINITY, tm1 = -INFINITY;
#pragma unroll
            for (int nt = 0; nt < 8; nt++) {
                tm0 = fmaxf(tm0, fmaxf(s[mi][nt][0], s[mi][nt][1]));
                tm1 = fmaxf(tm1, fmaxf(s[mi][nt][2], s[mi][nt][3]));
            }
            tm0 = fmaxf(tm0, __shfl_xor_sync(0xffffffffu, tm0, 1));
            tm0 = fmaxf(tm0, __shfl_xor_sync(0xffffffffu, tm0, 2));
            tm1 = fmaxf(tm1, __shfl_xor_sync(0xffffffffu, tm1, 1));
            tm1 = fmaxf(tm1, __shfl_xor_sync(0xffffffffu, tm1, 2));
            float mn0 = fmaxf(mrow[mi][0], tm0), mn1 = fmaxf(mrow[mi][1], tm1);
            float a0 = __expf(mrow[mi][0] - mn0), a1 = __expf(mrow[mi][1] - mn1);
            mrow[mi][0] = mn0; mrow[mi][1] = mn1;

            float rs0 = 0.0f, rs1 = 0.0f;
            int mr = w32 + mi * 16;
#pragma unroll
            for (int nt = 0; nt < 8; nt++) {
                float p0 = __expf(s[mi][nt][0] - mn0);
                float p1 = __expf(s[mi][nt][1] - mn0);
                float p2 = __expf(s[mi][nt][2] - mn1);
                float p3 = __expf(s[mi][nt][3] - mn1);
                rs0 += p0 + p1; rs1 += p2 + p3;
                int col = nt * 8 + 2 * c;
                Ps[(mr + r) * 68 + col]         = f2tf(p0);
                Ps[(mr + r) * 68 + col + 1]     = f2tf(p1);
                Ps[(mr + r + 8) * 68 + col]     = f2tf(p2);
                Ps[(mr + r + 8) * 68 + col + 1] = f2tf(p3);
            }
            rs0 += __shfl_xor_sync(0xffffffffu, rs0, 1);
            rs0 += __shfl_xor_sync(0xffffffffu, rs0, 2);
            rs1 += __shfl_xor_sync(0xffffffffu, rs1, 1);
            rs1 += __shfl_xor_sync(0xffffffffu, rs1, 2);
            lrow[mi][0] = lrow[mi][0] * a0 + rs0;
            lrow[mi][1] = lrow[mi][1] * a1 + rs1;
#pragma unroll
            for (int nt = 0; nt < 8; nt++) {
                o[mi][nt][0] *= a0; o[mi][nt][1] *= a0;
                o[mi][nt][2] *= a1; o[mi][nt][3] *= a1;
            }
        }
        __syncwarp();   // P rows are warp-private

        // O += P @ V
        uint32_t pa[2][4];
#pragma unroll
        for (int ks = 0; ks < 8; ks++) {
#pragma unroll
            for (int mi = 0; mi < 2; mi++) {
                int mr = w32 + mi * 16;
                pa[mi][0] = Ps[(mr + r) * 68 + ks * 8 + c];
                pa[mi][1] = Ps[(mr + r + 8) * 68 + ks * 8 + c];
                pa[mi][2] = Ps[(mr + r) * 68 + ks * 8 + c + 4];
                pa[mi][3] = Ps[(mr + r + 8) * 68 + ks * 8 + c + 4];
            }
#pragma unroll
            for (int nt = 0; nt < 8; nt++) {
                uint32_t b0 = Vsb[(ks * 8 + c) * 72 + nt * 8 + r];
                uint32_t b1 = Vsb[(ks * 8 + c + 4) * 72 + nt * 8 + r];
                mma8(o[0][nt], pa[0], b0, b1);
                mma8(o[1][nt], pa[1], b0, b1);
            }
        }
        __syncthreads();   // guard K/V buffer reuse
    }

    float* Ob = Out + ((size_t)b * L1 + q0) * 512 + h * 64;
#pragma unroll
    for (int mi = 0; mi < 2; mi++) {
        float inv0 = 1.0f / lrow[mi][0], inv1 = 1.0f / lrow[mi][1];
        int mr = w32 + mi * 16;
#pragma unroll
        for (int nt = 0; nt < 8; nt++) {
            int col = nt * 8 + 2 * c;
            float2 v0, v1;
            v0.x = gelu_exact(o[mi][nt][0] * inv0);
            v0.y = gelu_exact(o[mi][nt][1] * inv0);
            v1.x = gelu_exact(o[mi][nt][2] * inv1);
            v1.y = gelu_exact(o[mi][nt][3] * inv1);
            *(float2*)(Ob + (size_t)(mr + r) * 512 + col) = v0;
            *(float2*)(Ob + (size_t)(mr + r + 8) * 512 + col) = v1;
        }
    }
}

// ---------------- layernorm(E + A) -> tf32 ------------------------------------
__global__ __launch_bounds__(256) void ln_residual(const float* __restrict__ E,
                                                   const float* __restrict__ A,
                                                   const float* __restrict__ g,
                                                   const float* __restrict__ bb,
                                                   uint32_t* __restrict__ Out) {
    __shared__ float s1[256], s2[256];
    int tid = threadIdx.x;
    size_t base = (size_t)blockIdx.x * 512;
    float x0 = E[base + tid] + A[base + tid];
    float x1 = E[base + tid + 256] + A[base + tid + 256];
    s1[tid] = x0 + x1;
    s2[tid] = x0 * x0 + x1 * x1;
    __syncthreads();
    for (int s = 128; s > 0; s >>= 1) {
        if (tid < s) { s1[tid] += s1[tid + s]; s2[tid] += s2[tid + s]; }
        __syncthreads();
    }
    float mu  = s1[0] * (1.0f / 512.0f);
    float var = s2[0] * (1.0f / 512.0f) - mu * mu;
    float inv = rsqrtf(var + 1e-7f);
    Out[base + tid]       = f2tf((x0 - mu) * inv * g[tid]       + bb[tid]);
    Out[base + tid + 256] = f2tf((x1 - mu) * inv * g[tid + 256] + bb[tid + 256]);
}

// =============================================================================
extern "C" void kernel_launch(void* const* d_in, const int* in_sizes, int n_in,
                              void* d_out, int out_size) {
    const float* X    = (const float*)d_in[0];
    const int*   inc  = (const int*)d_in[1];
    const float* E    = (const float*)d_in[3];
    const float* Wqn  = (const float*)d_in[4];   const float* bqn = (const float*)d_in[5];
    const float* Wkn  = (const float*)d_in[6];   const float* bkn = (const float*)d_in[7];
    const float* Wvn  = (const float*)d_in[8];   const float* bvn = (const float*)d_in[9];
    const float* Wqe  = (const float*)d_in[10];  const float* bqe = (const float*)d_in[11];
    const float* Wke  = (const float*)d_in[12];  const float* bke = (const float*)d_in[13];
    const float* Wve  = (const float*)d_in[14];  const float* bve = (const float*)d_in[15];
    const float* Wm1  = (const float*)d_in[16];  const float* bm1 = (const float*)d_in[17];
    const float* Wm2  = (const float*)d_in[18];  const float* bm2 = (const float*)d_in[19];
    const float* g_ln = (const float*)d_in[20];  const float* b_ln = (const float*)d_in[21];

    float* out  = (float*)d_out;
    float* Xout = out;                              // [B,N,512]
    float* Eout = out + (size_t)Bc * Nn * Dd;       // [B,M,512]

    float* sc = nullptr;
    cudaGetSymbolAddress((void**)&sc, g_scratch);
    uint32_t* Qn    = (uint32_t*)(sc + OFF_QN);
    uint32_t* Kn    = (uint32_t*)(sc + OFF_KN);
    uint32_t* Vn    = (uint32_t*)(sc + OFF_VN);
    uint32_t* Qe    = (uint32_t*)(sc + OFF_QE);
    uint32_t* Ke    = (uint32_t*)(sc + OFF_KE);
    uint32_t* Ve    = (uint32_t*)(sc + OFF_VE);
    float*    Eattn = sc + OFF_EATTN;
    uint32_t* Eln   = (uint32_t*)(sc + OFF_ELN);
    uint32_t* Hid   = (uint32_t*)(sc + OFF_HID);
    uint32_t* pkO   = (uint32_t*)(sc + OFF_PKO);
    uint32_t* pkT   = (uint32_t*)(sc + OFF_PKT);
    uint32_t* Xc    = (uint32_t*)(sc + OFF_XC);
    uint32_t* Ec    = (uint32_t*)(sc + OFF_EC);
    uint32_t* Wc    = (uint32_t*)(sc + OFF_WC);
    uint32_t* Eoutc = (uint32_t*)(sc + OFF_EOUTC);

    static int attr_set = 0;
    if (!attr_set) {
        cudaFuncSetAttribute(flash_tc, cudaFuncAttributeMaxDynamicSharedMemorySize,
                             FLASH_SMEM);
        cudaFuncSetAttribute(sgemm_tc, cudaFuncAttributeMaxDynamicSharedMemorySize,
                             GEMM_SMEM);
        attr_set = 1;
    }

    // pre-conversions + mask packing
    conv_tf32<<<4096, 256>>>((const float4*)X, (uint4*)Xc, 1048576);
    conv_tf32<<<2048, 256>>>((const float4*)E, (uint4*)Ec, 524288);
    P8 wp; wp.p[0] = Wqn; wp.p[1] = Wkn; wp.p[2] = Wvn; wp.p[3] = Wqe;
    wp.p[4] = Wke; wp.p[5] = Wve; wp.p[6] = Wm1; wp.p[7] = Wm2;
    conv_w<<<dim3(256, 8), 256>>>(wp, Wc);
    pack_mask<<<(Bc * Nn * (Mm / 32)) / 256, 256>>>(inc, pkO);
    pack_maskT<<<dim3(Nn / 32, Mm / 32, Bc), dim3(32, 8)>>>(inc, pkT);

    GemmJobs jobs;
    // fused node QKV projections
    jobs.j[0] = { Wc + 0 * 262144, bqn, nullptr, Qn, 0, 1 };
    jobs.j[1] = { Wc + 1 * 262144, bkn, nullptr, Kn, 0, 1 };
    jobs.j[2] = { Wc + 2 * 262144, bvn, nullptr, Vn, 0, 1 };
    sgemm_tc<<<dim3(4, (Bc * Nn) / 128, 3), 256, GEMM_SMEM>>>(Xc, jobs);

    // edge Q projection
    jobs.j[0] = { Wc + 3 * 262144, bqe, nullptr, Qe, 0, 1 };
    jobs.j[1] = jobs.j[0]; jobs.j[2] = jobs.j[0];
    sgemm_tc<<<dim3(4, (Bc * Mm) / 128, 1), 256, GEMM_SMEM>>>(Ec, jobs);

    // stage 1: edges attend over nodes
    flash_tc<<<dim3(Mm / 128, Bc * Hh), 128, FLASH_SMEM>>>(Qe, Kn, Vn, pkT, Eattn,
                                                           Mm, Nn);

    // residual layernorm (fp32 in, tf32 out) + MLP
    ln_residual<<<Bc * Mm, 256>>>(E, Eattn, g_ln, b_ln, Eln);
    jobs.j[0] = { Wc + 6 * 262144, bm1, nullptr, Hid, 1, 1 };
    jobs.j[1] = jobs.j[0]; jobs.j[2] = jobs.j[0];
    sgemm_tc<<<dim3(4, (Bc * Mm) / 128, 1), 256, GEMM_SMEM>>>(Eln, jobs);
    jobs.j[0] = { Wc + 7 * 262144, bm2, Eout, Eoutc, 0, 2 };
    jobs.j[1] = jobs.j[0]; jobs.j[2] = jobs.j[0];
    sgemm_tc<<<dim3(4, (Bc * Mm) / 128, 1), 256, GEMM_SMEM>>>(Hid, jobs);

    // fused edge K/V projections from E_
    jobs.j[0] = { Wc + 4 * 262144, bke, nullptr, Ke, 0, 1 };
    jobs.j[1] = { Wc + 5 * 262144, bve, nullptr, Ve, 0, 1 };
    jobs.j[2] = jobs.j[0];
    sgemm_tc<<<dim3(4, (Bc * Mm) / 128, 2), 256, GEMM_SMEM>>>(Eoutc, jobs);

    // stage 2: nodes attend over edges
    flash_tc<<<dim3(Nn / 128, Bc * Hh), 128, FLASH_SMEM>>>(Qn, Ke, Ve, pkO, Xout,
                                                           Nn, Mm);
}

// round 7
// speedup vs baseline: 5.8635x; 1.2337x over previous
#include <cuda_runtime.h>
#include <cuda_fp16.h>
#include <math.h>
#include <stdint.h>

#define Bc 4
#define Nn 2048
#define Mm 1024
#define Dd 512
#define Hh 8
#define SCALE 0.125f
#define NEGV -9e15f

// ---------------- scratch (static device memory; no allocations) ------------
// float-indexed offsets
#define OFF_QNH   0ULL          /* half  B*N*512 = 2097152 fl */
#define OFF_KNH   2097152ULL
#define OFF_VTNH  4194304ULL    /* half, transposed per head  */
#define OFF_QEH   6291456ULL    /* half  B*M*512 = 1048576 fl */
#define OFF_KEH   7340032ULL
#define OFF_VTEH  8388608ULL
#define OFF_EATTN 9437184ULL    /* fp32 2097152 */
#define OFF_ELN   11534336ULL   /* tf32 2097152 */
#define OFF_HID   13631488ULL   /* tf32 2097152 */
#define OFF_PKO   15728640ULL
#define OFF_PKT   15990784ULL
#define OFF_XC    16252928ULL   /* tf32 X 4194304 */
#define OFF_EC    20447232ULL   /* tf32 E 2097152 */
#define OFF_WC    22544384ULL   /* tf32 weights 8x262144 */
#define OFF_EOUTC 24641536ULL   /* tf32 Eout 2097152 */
#define SCRATCH_FLOATS 26738688ULL

__device__ float g_scratch[SCRATCH_FLOATS];

__device__ __forceinline__ float gelu_exact(float x) {
    return 0.5f * x * (1.0f + erff(x * 0.70710678118654752f));
}

__device__ __forceinline__ uint32_t f2tf(float x) {
    uint32_t u;
    asm("cvt.rna.tf32.f32 %0, %1;" : "=r"(u) : "f"(x));
    return u;
}

__device__ __forceinline__ uint32_t pkh2(float a, float b) {
    __half2 h = __floats2half2_rn(a, b);
    return *(uint32_t*)&h;
}

__device__ __forceinline__ void mma8(float d[4], const uint32_t a[4],
                                     uint32_t b0, uint32_t b1) {
    asm volatile("mma.sync.aligned.m16n8k8.row.col.f32.tf32.tf32.f32 "
                 "{%0,%1,%2,%3}, {%4,%5,%6,%7}, {%8,%9}, {%0,%1,%2,%3};"
                 : "+f"(d[0]), "+f"(d[1]), "+f"(d[2]), "+f"(d[3])
                 : "r"(a[0]), "r"(a[1]), "r"(a[2]), "r"(a[3]),
                   "r"(b0), "r"(b1));
}

__device__ __forceinline__ void mma16(float d[4], const uint32_t a[4],
                                      uint32_t b0, uint32_t b1) {
    asm volatile("mma.sync.aligned.m16n8k16.row.col.f32.f16.f16.f32 "
                 "{%0,%1,%2,%3}, {%4,%5,%6,%7}, {%8,%9}, {%0,%1,%2,%3};"
                 : "+f"(d[0]), "+f"(d[1]), "+f"(d[2]), "+f"(d[3])
                 : "r"(a[0]), "r"(a[1]), "r"(a[2]), "r"(a[3]),
                   "r"(b0), "r"(b1));
}

__device__ __forceinline__ void cp16(uint32_t dst, const void* src) {
    asm volatile("cp.async.cg.shared.global [%0], [%1], 16;" :: "r"(dst), "l"(src));
}
#define CP_COMMIT() asm volatile("cp.async.commit_group;")
#define CP_WAIT(n)  asm volatile("cp.async.wait_group %0;" :: "n"(n))

// ---------------- tf32 pre-conversion ----------------------------------------
__global__ __launch_bounds__(256) void conv_tf32(const float4* __restrict__ in,
                                                 uint4* __restrict__ out, int n4) {
    int i = blockIdx.x * 256 + threadIdx.x;
    if (i < n4) {
        float4 v = in[i];
        out[i] = make_uint4(f2tf(v.x), f2tf(v.y), f2tf(v.z), f2tf(v.w));
    }
}

struct P8 { const float* p[8]; };
__global__ __launch_bounds__(256) void conv_w(P8 ws, uint32_t* __restrict__ out) {
    int g = blockIdx.y;
    int i = blockIdx.x * 256 + threadIdx.x;
    float4 v = ((const float4*)ws.p[g])[i];
    ((uint4*)(out + (size_t)g * 262144))[i] =
        make_uint4(f2tf(v.x), f2tf(v.y), f2tf(v.z), f2tf(v.w));
}

// ---------------- bit-pack masks ---------------------------------------------
__global__ __launch_bounds__(256) void pack_mask(const int* __restrict__ inc,
                                                 uint32_t* __restrict__ pk) {
    int w = blockIdx.x * 256 + threadIdx.x;
    int row = w >> 5, mw = w & 31;
    const int4* p = (const int4*)(inc + (size_t)row * Mm + mw * 32);
    uint32_t v = 0;
#pragma unroll
    for (int i = 0; i < 8; i++) {
        int4 q = p[i];
        v |= (q.x > 0 ? 1u : 0u) << (i * 4 + 0);
        v |= (q.y > 0 ? 1u : 0u) << (i * 4 + 1);
        v |= (q.z > 0 ? 1u : 0u) << (i * 4 + 2);
        v |= (q.w > 0 ? 1u : 0u) << (i * 4 + 3);
    }
    pk[w] = v;
}

__global__ void pack_maskT(const int* __restrict__ inc,
                           uint32_t* __restrict__ pk) {
    __shared__ int t[32][33];
    int b  = blockIdx.z;
    int n0 = blockIdx.x * 32;
    int m0 = blockIdx.y * 32;
    int tx = threadIdx.x, ty = threadIdx.y;
    for (int i = ty; i < 32; i += 8)
        t[i][tx] = inc[((size_t)b * Nn + n0 + i) * Mm + m0 + tx];
    __syncthreads();
    if (ty == 0) {
        uint32_t v = 0;
#pragma unroll
        for (int i = 0; i < 32; i++)
            v |= (t[i][tx] > 0 ? 1u : 0u) << i;
        pk[((size_t)b * Mm + m0 + tx) * (Nn / 32) + (n0 >> 5)] = v;
    }
}

// ---------------- tf32 SGEMM with cp.async pipeline ---------------------------
// modes: 0 fp32; 1 tf32; 2 fp32+tf32; 3 half(normal); 4 half transposed per head
struct GemmJob {
    const uint32_t* W;
    const float*    bias;
    void*           out0;
    void*           out1;
    int act;
    int mode;
    int vstride;   // mode 4: key-dim length (L2)
    int bshift;    // mode 4: log2(L2)
};
struct GemmJobs { GemmJob j[3]; };

#define GEMM_SMEM ((2 * 128 * 36 + 2 * 32 * 136) * 4)

__global__ __launch_bounds__(256) void sgemm_tc(const uint32_t* __restrict__ A,
                                                GemmJobs jobs) {
    extern __shared__ uint32_t sm[];
    uint32_t* As = sm;
    uint32_t* Ws = sm + 2 * 128 * 36;
    uint32_t asAddr = (uint32_t)__cvta_generic_to_shared(As);
    uint32_t wsAddr = (uint32_t)__cvta_generic_to_shared(Ws);

    const GemmJob J = jobs.j[blockIdx.z];
    int tid = threadIdx.x;
    int w = tid >> 5, lane = tid & 31;
    int r = lane >> 2, c = lane & 3;
    int wm = (w & 3) * 32;
    int wn = (w >> 2) * 64;
    int row0 = blockIdx.y * 128, col0 = blockIdx.x * 128;

    float acc[2][8][4];
#pragma unroll
    for (int mi = 0; mi < 2; mi++)
#pragma unroll
        for (int nt = 0; nt < 8; nt++)
#pragma unroll
            for (int j = 0; j < 4; j++) acc[mi][nt][j] = 0.0f;

    auto stage = [&](int buf, int kt) {
#pragma unroll
        for (int i = 0; i < 4; i++) {
            int lin = tid + i * 256;
            int m = lin >> 3, seg = lin & 7;
            cp16(asAddr + (((buf * 128 + m) * 36 + seg * 4) << 2),
                 A + (size_t)(row0 + m) * 512 + kt + seg * 4);
        }
#pragma unroll
        for (int i = 0; i < 4; i++) {
            int lin = tid + i * 256;
            int k = lin >> 5, seg = lin & 31;
            cp16(wsAddr + (((buf * 32 + k) * 136 + seg * 4) << 2),
                 J.W + (size_t)(kt + k) * 512 + col0 + seg * 4);
        }
    };

    stage(0, 0);
    CP_COMMIT();

    for (int kc = 0; kc < 16; kc++) {
        if (kc + 1 < 16) {
            stage((kc + 1) & 1, (kc + 1) * 32);
            CP_COMMIT();
            CP_WAIT(1);
        } else {
            CP_WAIT(0);
        }
        __syncthreads();
        const uint32_t* Ab = As + (kc & 1) * 128 * 36;
        const uint32_t* Wb = Ws + (kc & 1) * 32 * 136;
#pragma unroll
        for (int ks = 0; ks < 4; ks++) {
            uint32_t a[2][4];
#pragma unroll
            for (int mi = 0; mi < 2; mi++) {
                int mr = wm + mi * 16;
                a[mi][0] = Ab[(mr + r) * 36 + ks * 8 + c];
                a[mi][1] = Ab[(mr + r + 8) * 36 + ks * 8 + c];
                a[mi][2] = Ab[(mr + r) * 36 + ks * 8 + c + 4];
                a[mi][3] = Ab[(mr + r + 8) * 36 + ks * 8 + c + 4];
            }
#pragma unroll
            for (int nt = 0; nt < 8; nt++) {
                uint32_t b0 = Wb[(ks * 8 + c) * 136 + wn + nt * 8 + r];
                uint32_t b1 = Wb[(ks * 8 + c + 4) * 136 + wn + nt * 8 + r];
                mma8(acc[0][nt], a[0], b0, b1);
                mma8(acc[1][nt], a[1], b0, b1);
            }
        }
        __syncthreads();
    }

#pragma unroll
    for (int mi = 0; mi < 2; mi++) {
        int row = row0 + wm + mi * 16 + r;
#pragma unroll
        for (int nt = 0; nt < 8; nt++) {
            int col = col0 + wn + nt * 8 + 2 * c;
            float2 bv = *(const float2*)&J.bias[col];
            float x0 = acc[mi][nt][0] + bv.x, y0 = acc[mi][nt][1] + bv.y;
            float x1 = acc[mi][nt][2] + bv.x, y1 = acc[mi][nt][3] + bv.y;
            if (J.act) {
                x0 = gelu_exact(x0); y0 = gelu_exact(y0);
                x1 = gelu_exact(x1); y1 = gelu_exact(y1);
            }
            if (J.mode == 0 || J.mode == 2) {
                float* C = (float*)J.out0;
                *(float2*)&C[(size_t)row * 512 + col] = make_float2(x0, y0);
                *(float2*)&C[(size_t)(row + 8) * 512 + col] = make_float2(x1, y1);
            }
            if (J.mode == 1) {
                uint32_t* Cc = (uint32_t*)J.out0;
                *(uint2*)&Cc[(size_t)row * 512 + col] = make_uint2(f2tf(x0), f2tf(y0));
                *(uint2*)&Cc[(size_t)(row + 8) * 512 + col] = make_uint2(f2tf(x1), f2tf(y1));
            }
            if (J.mode == 2) {
                uint32_t* Cc = (uint32_t*)J.out1;
                *(uint2*)&Cc[(size_t)row * 512 + col] = make_uint2(f2tf(x0), f2tf(y0));
                *(uint2*)&Cc[(size_t)(row + 8) * 512 + col] = make_uint2(f2tf(x1), f2tf(y1));
            }
            if (J.mode == 3) {
                uint32_t* Ch = (uint32_t*)J.out0;   // half2-packed
                Ch[((size_t)row * 512 + col) >> 1] = pkh2(x0, y0);
                Ch[((size_t)(row + 8) * 512 + col) >> 1] = pkh2(x1, y1);
            }
            if (J.mode == 4) {
                __half* VT = (__half*)J.out0;
                int h = col >> 6, dd = col & 63;
                int bb = row >> J.bshift;
                int key = row & ((1 << J.bshift) - 1);
                size_t base = ((size_t)(bb * 8 + h) * 64 + dd) * J.vstride;
                size_t base1 = base + J.vstride;   // dd+1
                VT[base + key]      = __float2half_rn(x0);
                VT[base1 + key]     = __float2half_rn(y0);
                VT[base + key + 8]  = __float2half_rn(x1);
                VT[base1 + key + 8] = __float2half_rn(y1);
            }
        }
    }
}

// ---------------- fp16 flash attention ----------------------------------------
// 128 threads / 4 warps; Q tile 128 rows; warp owns 32 rows (mi=2).
// K: half [b][key][512] head slice. VT: half [(b*8+h)*64+d][key].
// m16n8k16 fp16 mma, fp32 accumulators; mask/softmax identical layout to tf32.
#define KT_ST 2304   /* 64*36 u32 */
#define FLASH_SMEM ((2 * KT_ST + 2 * KT_ST + 128 * 36) * 4)

__global__ __launch_bounds__(128) void flash_fp16(const __half* __restrict__ Q,
                                                  const __half* __restrict__ K,
                                                  const __half* __restrict__ VT,
                                                  const uint32_t* __restrict__ pk,
                                                  float* __restrict__ Out,
                                                  int L1, int L2) {
    extern __shared__ uint32_t fsm[];
    uint32_t* Kt = fsm;                    // [2][64][36] half2
    uint32_t* Vt = fsm + 2 * KT_ST;        // [2][64][36] half2 (rows = dim)
    uint32_t* Ps = fsm + 4 * KT_ST;        // [128][36]  Q stage / P tile
    uint32_t ktAddr = (uint32_t)__cvta_generic_to_shared(Kt);
    uint32_t vtAddr = (uint32_t)__cvta_generic_to_shared(Vt);
    uint32_t psAddr = (uint32_t)__cvta_generic_to_shared(Ps);

    int tid = threadIdx.x;
    int w = tid >> 5, lane = tid & 31;
    int r = lane >> 2, c = lane & 3;
    int w32 = w * 32;
    int bh = blockIdx.y;
    int b = bh >> 3, h = bh & 7;
    int q0 = blockIdx.x * 128;

    const __half* Qb  = Q + ((size_t)b * L1 + q0) * 512 + h * 64;
    const __half* Kb  = K + ((size_t)b * L2) * 512 + h * 64;
    const __half* VTb = VT + ((size_t)(b * 8 + h) * 64) * L2;
    int nw = L2 >> 5;
    const uint32_t* pr[2][2];
#pragma unroll
    for (int mi = 0; mi < 2; mi++) {
        pr[mi][0] = pk + ((size_t)b * L1 + q0 + w32 + mi * 16 + r) * nw;
        pr[mi][1] = pk + ((size_t)b * L1 + q0 + w32 + mi * 16 + r + 8) * nw;
    }

    auto stageKV = [&](int buf, int n0) {
        // K: 64 key-rows x 64 half (128B = 8 cp16)
#pragma unroll
        for (int i = 0; i < 4; i++) {
            int lin = tid + i * 128;
            int row = lin >> 3, seg = lin & 7;
            cp16(ktAddr + ((buf * KT_ST + row * 36 + seg * 4) << 2),
                 Kb + (size_t)(n0 + row) * 512 + seg * 8);
        }
        // VT: 64 dim-rows x 64 half keys
#pragma unroll
        for (int i = 0; i < 4; i++) {
            int lin = tid + i * 128;
            int row = lin >> 3, seg = lin & 7;
            cp16(vtAddr + ((buf * KT_ST + row * 36 + seg * 4) << 2),
                 VTb + (size_t)row * L2 + n0 + seg * 8);
        }
    };

    // stage Q (128 rows x 64 half) into Ps
#pragma unroll
    for (int i = 0; i < 8; i++) {
        int lin = tid + i * 128;
        int row = lin >> 3, seg = lin & 7;
        cp16(psAddr + ((row * 36 + seg * 4) << 2),
             Qb + (size_t)row * 512 + seg * 8);
    }
    stageKV(0, 0);
    CP_COMMIT();
    CP_WAIT(0);
    __syncthreads();

    uint32_t qa[2][4][4];
#pragma unroll
    for (int mi = 0; mi < 2; mi++) {
        int mr = w32 + mi * 16;
#pragma unroll
        for (int ks = 0; ks < 4; ks++) {
            qa[mi][ks][0] = Ps[(mr + r) * 36 + ks * 8 + c];
            qa[mi][ks][1] = Ps[(mr + r + 8) * 36 + ks * 8 + c];
            qa[mi][ks][2] = Ps[(mr + r) * 36 + ks * 8 + c + 4];
            qa[mi][ks][3] = Ps[(mr + r + 8) * 36 + ks * 8 + c + 4];
        }
    }
    __syncthreads();   // everyone has Q frags; Ps becomes P storage

    // re-prime the pipeline for tile 1 (stage after Q consumed)
    float o[2][8][4];
#pragma unroll
    for (int mi = 0; mi < 2; mi++)
#pragma unroll
        for (int nt = 0; nt < 8; nt++)
#pragma unroll
            for (int j = 0; j < 4; j++) o[mi][nt][j] = 0.0f;
    float mrow[2][2], lrow[2][2];
#pragma unroll
    for (int mi = 0; mi < 2; mi++) {
        mrow[mi][0] = -INFINITY; mrow[mi][1] = -INFINITY;
        lrow[mi][0] = 0.0f; lrow[mi][1] = 0.0f;
    }

    int T = L2 >> 6;
    for (int t = 0; t < T; t++) {
        int n0 = t << 6;
        if (t + 1 < T) {
            stageKV((t + 1) & 1, n0 + 64);
            CP_COMMIT();
            CP_WAIT(1);
        } else {
            CP_WAIT(0);
        }
        uint32_t mw[2][2][2];
#pragma unroll
        for (int mi = 0; mi < 2; mi++)
#pragma unroll
            for (int hf = 0; hf < 2; hf++) {
                mw[mi][hf][0] = __ldg(pr[mi][hf] + (n0 >> 5));
                mw[mi][hf][1] = __ldg(pr[mi][hf] + (n0 >> 5) + 1);
            }
        __syncthreads();
        const uint32_t* Ktb = Kt + (t & 1) * KT_ST;
        const uint32_t* Vtb = Vt + (t & 1) * KT_ST;

        // S = Q @ K^T (fp16 k16)
        float s[2][8][4];
#pragma unroll
        for (int mi = 0; mi < 2; mi++)
#pragma unroll
            for (int nt = 0; nt < 8; nt++)
#pragma unroll
                for (int j = 0; j < 4; j++) s[mi][nt][j] = 0.0f;
#pragma unroll
        for (int ks = 0; ks < 4; ks++) {
#pragma unroll
            for (int nt = 0; nt < 8; nt++) {
                uint32_t b0 = Ktb[(nt * 8 + r) * 36 + ks * 8 + c];
                uint32_t b1 = Ktb[(nt * 8 + r) * 36 + ks * 8 + c + 4];
                mma16(s[0][nt], qa[0][ks], b0, b1);
                mma16(s[1][nt], qa[1][ks], b0, b1);
            }
        }

        // mask + scale + online softmax (accumulator layout same as tf32 path)
#pragma unroll
        for (int mi = 0; mi < 2; mi++) {
#pragma unroll
            for (int nt = 0; nt < 8; nt++) {
                int k0 = nt * 8 + 2 * c;
                uint32_t wr0 = (k0 < 32) ? mw[mi][0][0] : mw[mi][0][1];
                uint32_t wr1 = (k0 < 32) ? mw[mi][1][0] : mw[mi][1][1];
                int sh = k0 & 31;
                s[mi][nt][0] = ((wr0 >> sh) & 1u)       ? s[mi][nt][0] * SCALE : NEGV;
                s[mi][nt][1] = ((wr0 >> (sh + 1)) & 1u) ? s[mi][nt][1] * SCALE : NEGV;
                s[mi][nt][2] = ((wr1 >> sh) & 1u)       ? s[mi][nt][2] * SCALE : NEGV;
                s[mi][nt][3] = ((wr1 >> (sh + 1)) & 1u) ? s[mi][nt][3] * SCALE : NEGV;
            }

            float tm0 = -INFINITY, tm1 = -INFINITY;
#pragma unroll
            for (int nt = 0; nt < 8; nt++) {
                tm0 = fmaxf(tm0, fmaxf(s[mi][nt][0], s[mi][nt][1]));
                tm1 = fmaxf(tm1, fmaxf(s[mi][nt][2], s[mi][nt][3]));
            }
            tm0 = fmaxf(tm0, __shfl_xor_sync(0xffffffffu, tm0, 1));
            tm0 = fmaxf(tm0, __shfl_xor_sync(0xffffffffu, tm0, 2));
            tm1 = fmaxf(tm1, __shfl_xor_sync(0xffffffffu, tm1, 1));
            tm1 = fmaxf(tm1, __shfl_xor_sync(0xffffffffu, tm1, 2));
            float mn0 = fmaxf(mrow[mi][0], tm0), mn1 = fmaxf(mrow[mi][1], tm1);
            float a0 = __expf(mrow[mi][0] - mn0), a1 = __expf(mrow[mi][1] - mn1);
            mrow[mi][0] = mn0; mrow[mi][1] = mn1;

            float rs0 = 0.0f, rs1 = 0.0f;
            int mr = w32 + mi * 16;
#pragma unroll
            for (int nt = 0; nt < 8; nt++) {
                float p0 = __expf(s[mi][nt][0] - mn0);
                float p1 = __expf(s[mi][nt][1] - mn0);
                float p2 = __expf(s[mi][nt][2] - mn1);
                float p3 = __expf(s[mi][nt][3] - mn1);
                rs0 += p0 + p1; rs1 += p2 + p3;
                Ps[(mr + r) * 36 + nt * 4 + c]     = pkh2(p0, p1);
                Ps[(mr + r + 8) * 36 + nt * 4 + c] = pkh2(p2, p3);
            }
            rs0 += __shfl_xor_sync(0xffffffffu, rs0, 1);
            rs0 += __shfl_xor_sync(0xffffffffu, rs0, 2);
            rs1 += __shfl_xor_sync(0xffffffffu, rs1, 1);
            rs1 += __shfl_xor_sync(0xffffffffu, rs1, 2);
            lrow[mi][0] = lrow[mi][0] * a0 + rs0;
            lrow[mi][1] = lrow[mi][1] * a1 + rs1;
#pragma unroll
            for (int nt = 0; nt < 8; nt++) {
                o[mi][nt][0] *= a0; o[mi][nt][1] *= a0;
                o[mi][nt][2] *= a1; o[mi][nt][3] *= a1;
            }
        }
        __syncwarp();   // P rows are warp-private

        // O += P @ V (fp16 k16; V frags shared across m-subtiles)
        uint32_t pa[2][4];
#pragma unroll
        for (int kt = 0; kt < 4; kt++) {
#pragma unroll
            for (int mi = 0; mi < 2; mi++) {
                int mr = w32 + mi * 16;
                pa[mi][0] = Ps[(mr + r) * 36 + kt * 8 + c];
                pa[mi][1] = Ps[(mr + r + 8) * 36 + kt * 8 + c];
                pa[mi][2] = Ps[(mr + r) * 36 + kt * 8 + c + 4];
                pa[mi][3] = Ps[(mr + r + 8) * 36 + kt * 8 + c + 4];
            }
#pragma unroll
            for (int nt = 0; nt < 8; nt++) {
                uint32_t b0 = Vtb[(nt * 8 + r) * 36 + kt * 8 + c];
                uint32_t b1 = Vtb[(nt * 8 + r) * 36 + kt * 8 + c + 4];
                mma16(o[0][nt], pa[0], b0, b1);
                mma16(o[1][nt], pa[1], b0, b1);
            }
        }
        __syncthreads();   // guard K/V buffer reuse
    }

    float* Ob = Out + ((size_t)b * L1 + q0) * 512 + h * 64;
#pragma unroll
    for (int mi = 0; mi < 2; mi++) {
        float inv0 = 1.0f / lrow[mi][0], inv1 = 1.0f / lrow[mi][1];
        int mr = w32 + mi * 16;
#pragma unroll
        for (int nt = 0; nt < 8; nt++) {
            int col = nt * 8 + 2 * c;
            float2 v0, v1;
            v0.x = gelu_exact(o[mi][nt][0] * inv0);
            v0.y = gelu_exact(o[mi][nt][1] * inv0);
            v1.x = gelu_exact(o[mi][nt][2] * inv1);
            v1.y = gelu_exact(o[mi][nt][3] * inv1);
            *(float2*)(Ob + (size_t)(mr + r) * 512 + col) = v0;
            *(float2*)(Ob + (size_t)(mr + r + 8) * 512 + col) = v1;
        }
    }
}

// ---------------- layernorm(E + A) -> tf32 ------------------------------------
__global__ __launch_bounds__(256) void ln_residual(const float* __restrict__ E,
                                                   const float* __restrict__ A,
                                                   const float* __restrict__ g,
                                                   const float* __restrict__ bb,
                                                   uint32_t* __restrict__ Out) {
    __shared__ float s1[256], s2[256];
    int tid = threadIdx.x;
    size_t base = (size_t)blockIdx.x * 512;
    float x0 = E[base + tid] + A[base + tid];
    float x1 = E[base + tid + 256] + A[base + tid + 256];
    s1[tid] = x0 + x1;
    s2[tid] = x0 * x0 + x1 * x1;
    __syncthreads();
    for (int s = 128; s > 0; s >>= 1) {
        if (tid < s) { s1[tid] += s1[tid + s]; s2[tid] += s2[tid + s]; }
        __syncthreads();
    }
    float mu  = s1[0] * (1.0f / 512.0f);
    float var = s2[0] * (1.0f / 512.0f) - mu * mu;
    float inv = rsqrtf(var + 1e-7f);
    Out[base + tid]       = f2tf((x0 - mu) * inv * g[tid]       + bb[tid]);
    Out[base + tid + 256] = f2tf((x1 - mu) * inv * g[tid + 256] + bb[tid + 256]);
}

// =============================================================================
extern "C" void kernel_launch(void* const* d_in, const int* in_sizes, int n_in,
                              void* d_out, int out_size) {
    const float* X    = (const float*)d_in[0];
    const int*   inc  = (const int*)d_in[1];
    const float* E    = (const float*)d_in[3];
    const float* Wqn  = (const float*)d_in[4];   const float* bqn = (const float*)d_in[5];
    const float* Wkn  = (const float*)d_in[6];   const float* bkn = (const float*)d_in[7];
    const float* Wvn  = (const float*)d_in[8];   const float* bvn = (const float*)d_in[9];
    const float* Wqe  = (const float*)d_in[10];  const float* bqe = (const float*)d_in[11];
    const float* Wke  = (const float*)d_in[12];  const float* bke = (const float*)d_in[13];
    const float* Wve  = (const float*)d_in[14];  const float* bve = (const float*)d_in[15];
    const float* Wm1  = (const float*)d_in[16];  const float* bm1 = (const float*)d_in[17];
    const float* Wm2  = (const float*)d_in[18];  const float* bm2 = (const float*)d_in[19];
    const float* g_ln = (const float*)d_in[20];  const float* b_ln = (const float*)d_in[21];

    float* out  = (float*)d_out;
    float* Xout = out;                              // [B,N,512]
    float* Eout = out + (size_t)Bc * Nn * Dd;       // [B,M,512]

    float* sc = nullptr;
    cudaGetSymbolAddress((void**)&sc, g_scratch);
    __half*   QnH   = (__half*)(sc + OFF_QNH);
    __half*   KnH   = (__half*)(sc + OFF_KNH);
    __half*   VTnH  = (__half*)(sc + OFF_VTNH);
    __half*   QeH   = (__half*)(sc + OFF_QEH);
    __half*   KeH   = (__half*)(sc + OFF_KEH);
    __half*   VTeH  = (__half*)(sc + OFF_VTEH);
    float*    Eattn = sc + OFF_EATTN;
    uint32_t* Eln   = (uint32_t*)(sc + OFF_ELN);
    uint32_t* Hid   = (uint32_t*)(sc + OFF_HID);
    uint32_t* pkO   = (uint32_t*)(sc + OFF_PKO);
    uint32_t* pkT   = (uint32_t*)(sc + OFF_PKT);
    uint32_t* Xc    = (uint32_t*)(sc + OFF_XC);
    uint32_t* Ec    = (uint32_t*)(sc + OFF_EC);
    uint32_t* Wc    = (uint32_t*)(sc + OFF_WC);
    uint32_t* Eoutc = (uint32_t*)(sc + OFF_EOUTC);

    static int attr_set = 0;
    if (!attr_set) {
        cudaFuncSetAttribute(flash_fp16, cudaFuncAttributeMaxDynamicSharedMemorySize,
                             FLASH_SMEM);
        cudaFuncSetAttribute(sgemm_tc, cudaFuncAttributeMaxDynamicSharedMemorySize,
                             GEMM_SMEM);
        attr_set = 1;
    }

    // prologue: tf32 conversions + mask packing
    conv_tf32<<<4096, 256>>>((const float4*)X, (uint4*)Xc, 1048576);
    conv_tf32<<<2048, 256>>>((const float4*)E, (uint4*)Ec, 524288);
    P8 wp; wp.p[0] = Wqn; wp.p[1] = Wkn; wp.p[2] = Wvn; wp.p[3] = Wqe;
    wp.p[4] = Wke; wp.p[5] = Wve; wp.p[6] = Wm1; wp.p[7] = Wm2;
    conv_w<<<dim3(256, 8), 256>>>(wp, Wc);
    pack_mask<<<(Bc * Nn * (Mm / 32)) / 256, 256>>>(inc, pkO);
    pack_maskT<<<dim3(Nn / 32, Mm / 32, Bc), dim3(32, 8)>>>(inc, pkT);

    GemmJobs jobs;
    // node QKV projections -> half (V transposed per head, key-stride Nn)
    jobs.j[0] = { Wc + 0 * 262144, bqn, QnH,  nullptr, 0, 3, 0, 0 };
    jobs.j[1] = { Wc + 1 * 262144, bkn, KnH,  nullptr, 0, 3, 0, 0 };
    jobs.j[2] = { Wc + 2 * 262144, bvn, VTnH, nullptr, 0, 4, Nn, 11 };
    sgemm_tc<<<dim3(4, (Bc * Nn) / 128, 3), 256, GEMM_SMEM>>>(Xc, jobs);

    // edge Q projection -> half
    jobs.j[0] = { Wc + 3 * 262144, bqe, QeH, nullptr, 0, 3, 0, 0 };
    jobs.j[1] = jobs.j[0]; jobs.j[2] = jobs.j[0];
    sgemm_tc<<<dim3(4, (Bc * Mm) / 128, 1), 256, GEMM_SMEM>>>(Ec, jobs);

    // stage 1: edges attend over nodes
    flash_fp16<<<dim3(Mm / 128, Bc * Hh), 128, FLASH_SMEM>>>(QeH, KnH, VTnH, pkT,
                                                             Eattn, Mm, Nn);

    // residual layernorm + MLP
    ln_residual<<<Bc * Mm, 256>>>(E, Eattn, g_ln, b_ln, Eln);
    jobs.j[0] = { Wc + 6 * 262144, bm1, Hid, nullptr, 1, 1, 0, 0 };
    jobs.j[1] = jobs.j[0]; jobs.j[2] = jobs.j[0];
    sgemm_tc<<<dim3(4, (Bc * Mm) / 128, 1), 256, GEMM_SMEM>>>(Eln, jobs);
    jobs.j[0] = { Wc + 7 * 262144, bm2, Eout, Eoutc, 0, 2, 0, 0 };
    jobs.j[1] = jobs.j[0]; jobs.j[2] = jobs.j[0];
    sgemm_tc<<<dim3(4, (Bc * Mm) / 128, 1), 256, GEMM_SMEM>>>(Hid, jobs);

    // edge K/V projections from E_ -> half (V transposed, key-stride Mm)
    jobs.j[0] = { Wc + 4 * 262144, bke, KeH,  nullptr, 0, 3, 0, 0 };
    jobs.j[1] = { Wc + 5 * 262144, bve, VTeH, nullptr, 0, 4, Mm, 10 };
    jobs.j[2] = jobs.j[0];
    sgemm_tc<<<dim3(4, (Bc * Mm) / 128, 2), 256, GEMM_SMEM>>>(Eoutc, jobs);

    // stage 2: nodes attend over edges
    flash_fp16<<<dim3(Nn / 128, Bc * Hh), 128, FLASH_SMEM>>>(QnH, KeH, VTeH, pkO,
                                                             Xout, Nn, Mm);
}

// round 8
// speedup vs baseline: 7.2100x; 1.2296x over previous
#include <cuda_runtime.h>
#include <cuda_fp16.h>
#include <math.h>
#include <stdint.h>

#define Bc 4
#define Nn 2048
#define Mm 1024
#define Dd 512
#define Hh 8
#define SCALE 0.125f
#define NEGV -9e15f

// ---------------- scratch (static device memory; no allocations) ------------
#define OFF_QNH   0ULL          /* half B*N*512 -> 2097152 fl */
#define OFF_KNH   2097152ULL
#define OFF_VTNH  4194304ULL
#define OFF_QEH   6291456ULL    /* half B*M*512 -> 1048576 fl */
#define OFF_KEH   7340032ULL
#define OFF_VTEH  8388608ULL
#define OFF_EATTN 9437184ULL    /* fp32 2097152 */
#define OFF_ELN   11534336ULL   /* half 1048576 */
#define OFF_HID   12582912ULL   /* half 1048576 */
#define OFF_PKO   13631488ULL   /* 262144 u32 */
#define OFF_PKT   13893632ULL   /* 262144 u32 */
#define OFF_XH    14155776ULL   /* half X 2097152 */
#define OFF_EH    16252928ULL   /* half E 1048576 */
#define OFF_WTH   17301504ULL   /* half Wt 8x512x512 -> 1048576 */
#define OFF_EOUTH 18350080ULL   /* half Eout 1048576 */
#define SCRATCH_FLOATS 19398656ULL

__device__ float g_scratch[SCRATCH_FLOATS];

__device__ __forceinline__ float gelu_exact(float x) {
    return 0.5f * x * (1.0f + erff(x * 0.70710678118654752f));
}

__device__ __forceinline__ uint32_t pkh2(float a, float b) {
    __half2 h = __floats2half2_rn(a, b);
    return *(uint32_t*)&h;
}

__device__ __forceinline__ void mma16(float d[4], const uint32_t a[4],
                                      uint32_t b0, uint32_t b1) {
    asm volatile("mma.sync.aligned.m16n8k16.row.col.f32.f16.f16.f32 "
                 "{%0,%1,%2,%3}, {%4,%5,%6,%7}, {%8,%9}, {%0,%1,%2,%3};"
                 : "+f"(d[0]), "+f"(d[1]), "+f"(d[2]), "+f"(d[3])
                 : "r"(a[0]), "r"(a[1]), "r"(a[2]), "r"(a[3]),
                   "r"(b0), "r"(b1));
}

__device__ __forceinline__ void cp16(uint32_t dst, const void* src) {
    asm volatile("cp.async.cg.shared.global [%0], [%1], 16;" :: "r"(dst), "l"(src));
}
#define CP_COMMIT() asm volatile("cp.async.commit_group;")
#define CP_WAIT(n)  asm volatile("cp.async.wait_group %0;" :: "n"(n))

// ---------------- fp16 pre-conversion ----------------------------------------
__global__ __launch_bounds__(256) void conv_h(const float4* __restrict__ in,
                                              uint2* __restrict__ out, int n4) {
    int i = blockIdx.x * 256 + threadIdx.x;
    if (i < n4) {
        float4 v = in[i];
        out[i] = make_uint2(pkh2(v.x, v.y), pkh2(v.z, v.w));
    }
}

// weights: W[k][n] fp32 -> Wt[n][k] half (per matrix), via 32x32 smem tiles
struct P8 { const float* p[8]; };
__global__ void conv_wt(P8 ws, __half* __restrict__ out) {
    __shared__ float t[32][33];
    int g = blockIdx.z;
    int k0 = blockIdx.x * 32, n0 = blockIdx.y * 32;
    const float* W = ws.p[g];
    int tx = threadIdx.x, ty = threadIdx.y;
#pragma unroll
    for (int i = 0; i < 4; i++)
        t[ty + 8 * i][tx] = W[(size_t)(k0 + ty + 8 * i) * 512 + n0 + tx];
    __syncthreads();
    __half* o = out + (size_t)g * 262144;
#pragma unroll
    for (int i = 0; i < 4; i++) {
        int row = ty + 8 * i;
        o[(size_t)(n0 + row) * 512 + k0 + tx] = __float2half_rn(t[tx][row]);
    }
}

// ---------------- fused mask pack (both orientations, one read) --------------
__global__ void pack_both(const int* __restrict__ inc,
                          uint32_t* __restrict__ pkO,
                          uint32_t* __restrict__ pkT) {
    __shared__ int t[32][33];
    int b  = blockIdx.z;
    int m0 = blockIdx.x * 32;
    int n0 = blockIdx.y * 32;
    int tx = threadIdx.x, ty = threadIdx.y;
#pragma unroll
    for (int i = ty; i < 32; i += 8)
        t[i][tx] = inc[((size_t)b * Nn + n0 + i) * Mm + m0 + tx];
    __syncthreads();
#pragma unroll
    for (int i = ty; i < 32; i += 8) {
        uint32_t vO = __ballot_sync(0xffffffffu, t[i][tx] > 0);
        uint32_t vT = __ballot_sync(0xffffffffu, t[tx][i] > 0);
        if (tx == 0) {
            pkO[((size_t)b * Nn + n0 + i) * (Mm / 32) + (m0 >> 5)] = vO;
            pkT[((size_t)b * Mm + m0 + i) * (Nn / 32) + (n0 >> 5)] = vT;
        }
    }
}

// ---------------- fp16 GEMM with cp.async pipeline ----------------------------
// C[R,512] = act(A[R,512] @ W + bias); A half [row][512], Wt half [n][k].
// block 128x128, 8 warps 4x2, warp 32x64, BK=64 halves, m16n8k16.
// modes: 0 fp32 out0; 2 fp32 out0 + half out1; 3 half out0; 4 half transposed per head
struct GemmJob {
    const uint32_t* W;     // Wt as half2 rows [n][k/2]
    const float*    bias;
    void*           out0;
    void*           out1;
    int act;
    int mode;
    int vstride;
    int bshift;
};
struct GemmJobs { GemmJob j[3]; };

#define GEMM_SMEM (2 * 128 * 36 * 4 * 2)

__global__ __launch_bounds__(256) void sgemm_h(const uint32_t* __restrict__ A,
                                               GemmJobs jobs) {
    extern __shared__ uint32_t sm[];
    uint32_t* As = sm;                 // [2][128][36] half2
    uint32_t* Ws = sm + 2 * 128 * 36;  // [2][128][36] half2 (rows = n)
    uint32_t asAddr = (uint32_t)__cvta_generic_to_shared(As);
    uint32_t wsAddr = (uint32_t)__cvta_generic_to_shared(Ws);

    const GemmJob J = jobs.j[blockIdx.z];
    int tid = threadIdx.x;
    int w = tid >> 5, lane = tid & 31;
    int r = lane >> 2, c = lane & 3;
    int wm = (w & 3) * 32;
    int wn = (w >> 2) * 64;
    int row0 = blockIdx.y * 128, col0 = blockIdx.x * 128;

    float acc[2][8][4];
#pragma unroll
    for (int mi = 0; mi < 2; mi++)
#pragma unroll
        for (int nt = 0; nt < 8; nt++)
#pragma unroll
            for (int j = 0; j < 4; j++) acc[mi][nt][j] = 0.0f;

    auto stage = [&](int buf, int kc) {
        int kt = kc * 32;   // u32 (half2) offset within row
#pragma unroll
        for (int i = 0; i < 4; i++) {
            int lin = tid + i * 256;
            int row = lin >> 3, seg = lin & 7;
            cp16(asAddr + (((buf * 128 + row) * 36 + seg * 4) << 2),
                 A + (size_t)(row0 + row) * 256 + kt + seg * 4);
        }
#pragma unroll
        for (int i = 0; i < 4; i++) {
            int lin = tid + i * 256;
            int row = lin >> 3, seg = lin & 7;
            cp16(wsAddr + (((buf * 128 + row) * 36 + seg * 4) << 2),
                 J.W + (size_t)(col0 + row) * 256 + kt + seg * 4);
        }
    };

    stage(0, 0);
    CP_COMMIT();

    for (int kc = 0; kc < 8; kc++) {
        if (kc + 1 < 8) {
            stage((kc + 1) & 1, kc + 1);
            CP_COMMIT();
            CP_WAIT(1);
        } else {
            CP_WAIT(0);
        }
        __syncthreads();
        const uint32_t* Ab = As + (kc & 1) * 128 * 36;
        const uint32_t* Wb = Ws + (kc & 1) * 128 * 36;
#pragma unroll
        for (int ks = 0; ks < 4; ks++) {
            uint32_t a[2][4];
#pragma unroll
            for (int mi = 0; mi < 2; mi++) {
                int mr = wm + mi * 16;
                a[mi][0] = Ab[(mr + r) * 36 + ks * 8 + c];
                a[mi][1] = Ab[(mr + r + 8) * 36 + ks * 8 + c];
                a[mi][2] = Ab[(mr + r) * 36 + ks * 8 + c + 4];
                a[mi][3] = Ab[(mr + r + 8) * 36 + ks * 8 + c + 4];
            }
#pragma unroll
            for (int nt = 0; nt < 8; nt++) {
                uint32_t b0 = Wb[(wn + nt * 8 + r) * 36 + ks * 8 + c];
                uint32_t b1 = Wb[(wn + nt * 8 + r) * 36 + ks * 8 + c + 4];
                mma16(acc[0][nt], a[0], b0, b1);
                mma16(acc[1][nt], a[1], b0, b1);
            }
        }
        __syncthreads();
    }

#pragma unroll
    for (int mi = 0; mi < 2; mi++) {
        int row = row0 + wm + mi * 16 + r;
#pragma unroll
        for (int nt = 0; nt < 8; nt++) {
            int col = col0 + wn + nt * 8 + 2 * c;
            float2 bv = *(const float2*)&J.bias[col];
            float x0 = acc[mi][nt][0] + bv.x, y0 = acc[mi][nt][1] + bv.y;
            float x1 = acc[mi][nt][2] + bv.x, y1 = acc[mi][nt][3] + bv.y;
            if (J.act) {
                x0 = gelu_exact(x0); y0 = gelu_exact(y0);
                x1 = gelu_exact(x1); y1 = gelu_exact(y1);
            }
            if (J.mode == 0 || J.mode == 2) {
                float* C = (float*)J.out0;
                *(float2*)&C[(size_t)row * 512 + col] = make_float2(x0, y0);
                *(float2*)&C[(size_t)(row + 8) * 512 + col] = make_float2(x1, y1);
            }
            if (J.mode == 2) {
                uint32_t* Ch = (uint32_t*)J.out1;
                Ch[((size_t)row * 512 + col) >> 1] = pkh2(x0, y0);
                Ch[((size_t)(row + 8) * 512 + col) >> 1] = pkh2(x1, y1);
            }
            if (J.mode == 3) {
                uint32_t* Ch = (uint32_t*)J.out0;
                Ch[((size_t)row * 512 + col) >> 1] = pkh2(x0, y0);
                Ch[((size_t)(row + 8) * 512 + col) >> 1] = pkh2(x1, y1);
            }
            if (J.mode == 4) {
                __half* VT = (__half*)J.out0;
                int h = col >> 6, dd = col & 63;
                int bb = row >> J.bshift;
                int key = row & ((1 << J.bshift) - 1);
                size_t base = ((size_t)(bb * 8 + h) * 64 + dd) * J.vstride;
                size_t base1 = base + J.vstride;
                VT[base + key]      = __float2half_rn(x0);
                VT[base1 + key]     = __float2half_rn(y0);
                VT[base + key + 8]  = __float2half_rn(x1);
                VT[base1 + key + 8] = __float2half_rn(y1);
            }
        }
    }
}

// ---------------- fp16 flash attention (unchanged from R7) --------------------
#define KT_ST 2304   /* 64*36 u32 */
#define FLASH_SMEM ((2 * KT_ST + 2 * KT_ST + 128 * 36) * 4)

__global__ __launch_bounds__(128) void flash_fp16(const __half* __restrict__ Q,
                                                  const __half* __restrict__ K,
                                                  const __half* __restrict__ VT,
                                                  const uint32_t* __restrict__ pk,
                                                  float* __restrict__ Out,
                                                  int L1, int L2) {
    extern __shared__ uint32_t fsm[];
    uint32_t* Kt = fsm;
    uint32_t* Vt = fsm + 2 * KT_ST;
    uint32_t* Ps = fsm + 4 * KT_ST;
    uint32_t ktAddr = (uint32_t)__cvta_generic_to_shared(Kt);
    uint32_t vtAddr = (uint32_t)__cvta_generic_to_shared(Vt);
    uint32_t psAddr = (uint32_t)__cvta_generic_to_shared(Ps);

    int tid = threadIdx.x;
    int w = tid >> 5, lane = tid & 31;
    int r = lane >> 2, c = lane & 3;
    int w32 = w * 32;
    int bh = blockIdx.y;
    int b = bh >> 3, h = bh & 7;
    int q0 = blockIdx.x * 128;

    const __half* Qb  = Q + ((size_t)b * L1 + q0) * 512 + h * 64;
    const __half* Kb  = K + ((size_t)b * L2) * 512 + h * 64;
    const __half* VTb = VT + ((size_t)(b * 8 + h) * 64) * L2;
    int nw = L2 >> 5;
    const uint32_t* pr[2][2];
#pragma unroll
    for (int mi = 0; mi < 2; mi++) {
        pr[mi][0] = pk + ((size_t)b * L1 + q0 + w32 + mi * 16 + r) * nw;
        pr[mi][1] = pk + ((size_t)b * L1 + q0 + w32 + mi * 16 + r + 8) * nw;
    }

    auto stageKV = [&](int buf, int n0) {
#pragma unroll
        for (int i = 0; i < 4; i++) {
            int lin = tid + i * 128;
            int row = lin >> 3, seg = lin & 7;
            cp16(ktAddr + ((buf * KT_ST + row * 36 + seg * 4) << 2),
                 Kb + (size_t)(n0 + row) * 512 + seg * 8);
        }
#pragma unroll
        for (int i = 0; i < 4; i++) {
            int lin = tid + i * 128;
            int row = lin >> 3, seg = lin & 7;
            cp16(vtAddr + ((buf * KT_ST + row * 36 + seg * 4) << 2),
                 VTb + (size_t)row * L2 + n0 + seg * 8);
        }
    };

#pragma unroll
    for (int i = 0; i < 8; i++) {
        int lin = tid + i * 128;
        int row = lin >> 3, seg = lin & 7;
        cp16(psAddr + ((row * 36 + seg * 4) << 2),
             Qb + (size_t)row * 512 + seg * 8);
    }
    stageKV(0, 0);
    CP_COMMIT();
    CP_WAIT(0);
    __syncthreads();

    uint32_t qa[2][4][4];
#pragma unroll
    for (int mi = 0; mi < 2; mi++) {
        int mr = w32 + mi * 16;
#pragma unroll
        for (int ks = 0; ks < 4; ks++) {
            qa[mi][ks][0] = Ps[(mr + r) * 36 + ks * 8 + c];
            qa[mi][ks][1] = Ps[(mr + r + 8) * 36 + ks * 8 + c];
            qa[mi][ks][2] = Ps[(mr + r) * 36 + ks * 8 + c + 4];
            qa[mi][ks][3] = Ps[(mr + r + 8) * 36 + ks * 8 + c + 4];
        }
    }
    __syncthreads();

    float o[2][8][4];
#pragma unroll
    for (int mi = 0; mi < 2; mi++)
#pragma unroll
        for (int nt = 0; nt < 8; nt++)
#pragma unroll
            for (int j = 0; j < 4; j++) o[mi][nt][j] = 0.0f;
    float mrow[2][2], lrow[2][2];
#pragma unroll
    for (int mi = 0; mi < 2; mi++) {
        mrow[mi][0] = -INFINITY; mrow[mi][1] = -INFINITY;
        lrow[mi][0] = 0.0f; lrow[mi][1] = 0.0f;
    }

    int T = L2 >> 6;
    for (int t = 0; t < T; t++) {
        int n0 = t << 6;
        if (t + 1 < T) {
            stageKV((t + 1) & 1, n0 + 64);
            CP_COMMIT();
            CP_WAIT(1);
        } else {
            CP_WAIT(0);
        }
        uint32_t mw[2][2][2];
#pragma unroll
        for (int mi = 0; mi < 2; mi++)
#pragma unroll
            for (int hf = 0; hf < 2; hf++) {
                mw[mi][hf][0] = __ldg(pr[mi][hf] + (n0 >> 5));
                mw[mi][hf][1] = __ldg(pr[mi][hf] + (n0 >> 5) + 1);
            }
        __syncthreads();
        const uint32_t* Ktb = Kt + (t & 1) * KT_ST;
        const uint32_t* Vtb = Vt + (t & 1) * KT_ST;

        float s[2][8][4];
#pragma unroll
        for (int mi = 0; mi < 2; mi++)
#pragma unroll
            for (int nt = 0; nt < 8; nt++)
#pragma unroll
                for (int j = 0; j < 4; j++) s[mi][nt][j] = 0.0f;
#pragma unroll
        for (int ks = 0; ks < 4; ks++) {
#pragma unroll
            for (int nt = 0; nt < 8; nt++) {
                uint32_t b0 = Ktb[(nt * 8 + r) * 36 + ks * 8 + c];
                uint32_t b1 = Ktb[(nt * 8 + r) * 36 + ks * 8 + c + 4];
                mma16(s[0][nt], qa[0][ks], b0, b1);
                mma16(s[1][nt], qa[1][ks], b0, b1);
            }
        }

#pragma unroll
        for (int mi = 0; mi < 2; mi++) {
#pragma unroll
            for (int nt = 0; nt < 8; nt++) {
                int k0 = nt * 8 + 2 * c;
                uint32_t wr0 = (k0 < 32) ? mw[mi][0][0] : mw[mi][0][1];
                uint32_t wr1 = (k0 < 32) ? mw[mi][1][0] : mw[mi][1][1];
                int sh = k0 & 31;
                s[mi][nt][0] = ((wr0 >> sh) & 1u)       ? s[mi][nt][0] * SCALE : NEGV;
                s[mi][nt][1] = ((wr0 >> (sh + 1)) & 1u) ? s[mi][nt][1] * SCALE : NEGV;
                s[mi][nt][2] = ((wr1 >> sh) & 1u)       ? s[mi][nt][2] * SCALE : NEGV;
                s[mi][nt][3] = ((wr1 >> (sh + 1)) & 1u) ? s[mi][nt][3] * SCALE : NEGV;
            }

            float tm0 = -INFINITY, tm1 = -INFINITY;
#pragma unroll
            for (int nt = 0; nt < 8; nt++) {
                tm0 = fmaxf(tm0, fmaxf(s[mi][nt][0], s[mi][nt][1]));
                tm1 = fmaxf(tm1, fmaxf(s[mi][nt][2], s[mi][nt][3]));
            }
            tm0 = fmaxf(tm0, __shfl_xor_sync(0xffffffffu, tm0, 1));
            tm0 = fmaxf(tm0, __shfl_xor_sync(0xffffffffu, tm0, 2));
            tm1 = fmaxf(tm1, __shfl_xor_sync(0xffffffffu, tm1, 1));
            tm1 = fmaxf(tm1, __shfl_xor_sync(0xffffffffu, tm1, 2));
            float mn0 = fmaxf(mrow[mi][0], tm0), mn1 = fmaxf(mrow[mi][1], tm1);
            float a0 = __expf(mrow[mi][0] - mn0), a1 = __expf(mrow[mi][1] - mn1);
            mrow[mi][0] = mn0; mrow[mi][1] = mn1;

            float rs0 = 0.0f, rs1 = 0.0f;
            int mr = w32 + mi * 16;
#pragma unroll
            for (int nt = 0; nt < 8; nt++) {
                float p0 = __expf(s[mi][nt][0] - mn0);
                float p1 = __expf(s[mi][nt][1] - mn0);
                float p2 = __expf(s[mi][nt][2] - mn1);
                float p3 = __expf(s[mi][nt][3] - mn1);
                rs0 += p0 + p1; rs1 += p2 + p3;
                Ps[(mr + r) * 36 + nt * 4 + c]     = pkh2(p0, p1);
                Ps[(mr + r + 8) * 36 + nt * 4 + c] = pkh2(p2, p3);
            }
            rs0 += __shfl_xor_sync(0xffffffffu, rs0, 1);
            rs0 += __shfl_xor_sync(0xffffffffu, rs0, 2);
            rs1 += __shfl_xor_sync(0xffffffffu, rs1, 1);
            rs1 += __shfl_xor_sync(0xffffffffu, rs1, 2);
            lrow[mi][0] = lrow[mi][0] * a0 + rs0;
            lrow[mi][1] = lrow[mi][1] * a1 + rs1;
#pragma unroll
            for (int nt = 0; nt < 8; nt++) {
                o[mi][nt][0] *= a0; o[mi][nt][1] *= a0;
                o[mi][nt][2] *= a1; o[mi][nt][3] *= a1;
            }
        }
        __syncwarp();

        uint32_t pa[2][4];
#pragma unroll
        for (int kt = 0; kt < 4; kt++) {
#pragma unroll
            for (int mi = 0; mi < 2; mi++) {
                int mr = w32 + mi * 16;
                pa[mi][0] = Ps[(mr + r) * 36 + kt * 8 + c];
                pa[mi][1] = Ps[(mr + r + 8) * 36 + kt * 8 + c];
                pa[mi][2] = Ps[(mr + r) * 36 + kt * 8 + c + 4];
                pa[mi][3] = Ps[(mr + r + 8) * 36 + kt * 8 + c + 4];
            }
#pragma unroll
            for (int nt = 0; nt < 8; nt++) {
                uint32_t b0 = Vtb[(nt * 8 + r) * 36 + kt * 8 + c];
                uint32_t b1 = Vtb[(nt * 8 + r) * 36 + kt * 8 + c + 4];
                mma16(o[0][nt], pa[0], b0, b1);
                mma16(o[1][nt], pa[1], b0, b1);
            }
        }
        __syncthreads();
    }

    float* Ob = Out + ((size_t)b * L1 + q0) * 512 + h * 64;
#pragma unroll
    for (int mi = 0; mi < 2; mi++) {
        float inv0 = 1.0f / lrow[mi][0], inv1 = 1.0f / lrow[mi][1];
        int mr = w32 + mi * 16;
#pragma unroll
        for (int nt = 0; nt < 8; nt++) {
            int col = nt * 8 + 2 * c;
            float2 v0, v1;
            v0.x = gelu_exact(o[mi][nt][0] * inv0);
            v0.y = gelu_exact(o[mi][nt][1] * inv0);
            v1.x = gelu_exact(o[mi][nt][2] * inv1);
            v1.y = gelu_exact(o[mi][nt][3] * inv1);
            *(float2*)(Ob + (size_t)(mr + r) * 512 + col) = v0;
            *(float2*)(Ob + (size_t)(mr + r + 8) * 512 + col) = v1;
        }
    }
}

// ---------------- layernorm(E + A) -> half ------------------------------------
__global__ __launch_bounds__(256) void ln_residual(const float* __restrict__ E,
                                                   const float* __restrict__ A,
                                                   const float* __restrict__ g,
                                                   const float* __restrict__ bb,
                                                   uint32_t* __restrict__ Out) {
    __shared__ float s1[256], s2[256];
    int tid = threadIdx.x;
    size_t base = (size_t)blockIdx.x * 512;
    float2 e = *(const float2*)&E[base + 2 * tid];
    float2 a = *(const float2*)&A[base + 2 * tid];
    float x0 = e.x + a.x, x1 = e.y + a.y;
    s1[tid] = x0 + x1;
    s2[tid] = x0 * x0 + x1 * x1;
    __syncthreads();
    for (int s = 128; s > 0; s >>= 1) {
        if (tid < s) { s1[tid] += s1[tid + s]; s2[tid] += s2[tid + s]; }
        __syncthreads();
    }
    float mu  = s1[0] * (1.0f / 512.0f);
    float var = s2[0] * (1.0f / 512.0f) - mu * mu;
    float inv = rsqrtf(var + 1e-7f);
    float2 gg = *(const float2*)&g[2 * tid];
    float2 bv = *(const float2*)&bb[2 * tid];
    Out[(base >> 1) + tid] = pkh2((x0 - mu) * inv * gg.x + bv.x,
                                  (x1 - mu) * inv * gg.y + bv.y);
}

// =============================================================================
extern "C" void kernel_launch(void* const* d_in, const int* in_sizes, int n_in,
                              void* d_out, int out_size) {
    const float* X    = (const float*)d_in[0];
    const int*   inc  = (const int*)d_in[1];
    const float* E    = (const float*)d_in[3];
    const float* Wqn  = (const float*)d_in[4];   const float* bqn = (const float*)d_in[5];
    const float* Wkn  = (const float*)d_in[6];   const float* bkn = (const float*)d_in[7];
    const float* Wvn  = (const float*)d_in[8];   const float* bvn = (const float*)d_in[9];
    const float* Wqe  = (const float*)d_in[10];  const float* bqe = (const float*)d_in[11];
    const float* Wke  = (const float*)d_in[12];  const float* bke = (const float*)d_in[13];
    const float* Wve  = (const float*)d_in[14];  const float* bve = (const float*)d_in[15];
    const float* Wm1  = (const float*)d_in[16];  const float* bm1 = (const float*)d_in[17];
    const float* Wm2  = (const float*)d_in[18];  const float* bm2 = (const float*)d_in[19];
    const float* g_ln = (const float*)d_in[20];  const float* b_ln = (const float*)d_in[21];

    float* out  = (float*)d_out;
    float* Xout = out;                              // [B,N,512]
    float* Eout = out + (size_t)Bc * Nn * Dd;       // [B,M,512]

    float* sc = nullptr;
    cudaGetSymbolAddress((void**)&sc, g_scratch);
    __half*   QnH   = (__half*)(sc + OFF_QNH);
    __half*   KnH   = (__half*)(sc + OFF_KNH);
    __half*   VTnH  = (__half*)(sc + OFF_VTNH);
    __half*   QeH   = (__half*)(sc + OFF_QEH);
    __half*   KeH   = (__half*)(sc + OFF_KEH);
    __half*   VTeH  = (__half*)(sc + OFF_VTEH);
    float*    Eattn = sc + OFF_EATTN;
    uint32_t* Eln   = (uint32_t*)(sc + OFF_ELN);
    uint32_t* Hid   = (uint32_t*)(sc + OFF_HID);
    uint32_t* pkO   = (uint32_t*)(sc + OFF_PKO);
    uint32_t* pkT   = (uint32_t*)(sc + OFF_PKT);
    uint32_t* Xh    = (uint32_t*)(sc + OFF_XH);
    uint32_t* Eh    = (uint32_t*)(sc + OFF_EH);
    __half*   Wt    = (__half*)(sc + OFF_WTH);
    uint32_t* Wtu   = (uint32_t*)(sc + OFF_WTH);
    uint32_t* EoutH = (uint32_t*)(sc + OFF_EOUTH);

    static int attr_set = 0;
    if (!attr_set) {
        cudaFuncSetAttribute(flash_fp16, cudaFuncAttributeMaxDynamicSharedMemorySize,
                             FLASH_SMEM);
        cudaFuncSetAttribute(sgemm_h, cudaFuncAttributeMaxDynamicSharedMemorySize,
                             GEMM_SMEM);
        attr_set = 1;
    }

    // prologue: half conversions + fused mask packing
    conv_h<<<4096, 256>>>((const float4*)X, (uint2*)Xh, 1048576);
    conv_h<<<2048, 256>>>((const float4*)E, (uint2*)Eh, 524288);
    P8 wp; wp.p[0] = Wqn; wp.p[1] = Wkn; wp.p[2] = Wvn; wp.p[3] = Wqe;
    wp.p[4] = Wke; wp.p[5] = Wve; wp.p[6] = Wm1; wp.p[7] = Wm2;
    conv_wt<<<dim3(16, 16, 8), dim3(32, 8)>>>(wp, Wt);
    pack_both<<<dim3(Mm / 32, Nn / 32, Bc), dim3(32, 8)>>>(inc, pkO, pkT);

    GemmJobs jobs;
    // node QKV projections (V transposed per head, key-stride Nn)
    jobs.j[0] = { Wtu + 0 * 131072, bqn, QnH,  nullptr, 0, 3, 0, 0 };
    jobs.j[1] = { Wtu + 1 * 131072, bkn, KnH,  nullptr, 0, 3, 0, 0 };
    jobs.j[2] = { Wtu + 2 * 131072, bvn, VTnH, nullptr, 0, 4, Nn, 11 };
    sgemm_h<<<dim3(4, (Bc * Nn) / 128, 3), 256, GEMM_SMEM>>>(Xh, jobs);

    // edge Q projection
    jobs.j[0] = { Wtu + 3 * 131072, bqe, QeH, nullptr, 0, 3, 0, 0 };
    jobs.j[1] = jobs.j[0]; jobs.j[2] = jobs.j[0];
    sgemm_h<<<dim3(4, (Bc * Mm) / 128, 1), 256, GEMM_SMEM>>>(Eh, jobs);

    // stage 1: edges attend over nodes
    flash_fp16<<<dim3(Mm / 128, Bc * Hh), 128, FLASH_SMEM>>>(QeH, KnH, VTnH, pkT,
                                                             Eattn, Mm, Nn);

    // residual layernorm + MLP
    ln_residual<<<Bc * Mm, 256>>>(E, Eattn, g_ln, b_ln, Eln);
    jobs.j[0] = { Wtu + 6 * 131072, bm1, Hid, nullptr, 1, 3, 0, 0 };
    jobs.j[1] = jobs.j[0]; jobs.j[2] = jobs.j[0];
    sgemm_h<<<dim3(4, (Bc * Mm) / 128, 1), 256, GEMM_SMEM>>>(Eln, jobs);
    jobs.j[0] = { Wtu + 7 * 131072, bm2, Eout, EoutH, 0, 2, 0, 0 };
    jobs.j[1] = jobs.j[0]; jobs.j[2] = jobs.j[0];
    sgemm_h<<<dim3(4, (Bc * Mm) / 128, 1), 256, GEMM_SMEM>>>(Hid, jobs);

    // edge K/V projections from E_ (V transposed, key-stride Mm)
    jobs.j[0] = { Wtu + 4 * 131072, bke, KeH,  nullptr, 0, 3, 0, 0 };
    jobs.j[1] = { Wtu + 5 * 131072, bve, VTeH, nullptr, 0, 4, Mm, 10 };
    jobs.j[2] = jobs.j[0];
    sgemm_h<<<dim3(4, (Bc * Mm) / 128, 2), 256, GEMM_SMEM>>>(EoutH, jobs);

    // stage 2: nodes attend over edges
    flash_fp16<<<dim3(Nn / 128, Bc * Hh), 128, FLASH_SMEM>>>(QnH, KeH, VTeH, pkO,
                                                             Xout, Nn, Mm);
}